// round 14
// baseline (speedup 1.0000x reference)
#include <cuda_runtime.h>
#include <cuda_bf16.h>
#include <cstdint>

#define Bq 2048
#define Tq 128
#define Nq (Bq*Tq)

// ---------------- scratch (no allocations allowed) ----------------
__device__ float g_air[(size_t)Nq * 32];
__device__ float g_m1 [(size_t)Nq * 32];
__device__ float g_m2 [(size_t)Nq * 32];
__device__ float g_fusion[(size_t)Nq * 64];
// MLP weights prepacked in mma B-fragment layout (hi/lo split-bf16)
__device__ uint2 g_W0f[8192];    // [k16(4)][ntg(32)][part(2)][lane(32)]
__device__ uint2 g_W1f[32768];   // [ck(16)][ntg(32)][part(2)][lane(32)]
// GRU tensor-core prepack: B-fragments, biases, X A-fragments
__device__ uint2  g_gB[2 * 36 * 2 * 32];
__device__ float  g_gBias[2 * 128];
__device__ uint4  g_gX[(size_t)384 * 128 * 32 * 2];

__device__ __forceinline__ float tanhap(float x) {
    float y;
    asm("tanh.approx.f32 %0, %1;" : "=f"(y) : "f"(x));
    return y;
}
__device__ __forceinline__ float fsig(float x) {
    return fmaf(0.5f, tanhap(0.5f * x), 0.5f);
}

union F2U { float2 f; unsigned long long u; };
__device__ __forceinline__ float2 ffma2(float2 a, float2 b, float2 c) {
    F2U A, B, C, D;
    A.f = a; B.f = b; C.f = c;
    asm("fma.rn.f32x2 %0, %1, %2, %3;" : "=l"(D.u) : "l"(A.u), "l"(B.u), "l"(C.u));
    return D.f;
}
__device__ __forceinline__ float2 dot4_2(float4 a, float4 b, float2 acc) {
    acc = ffma2(make_float2(a.x, a.y), make_float2(b.x, b.y), acc);
    acc = ffma2(make_float2(a.z, a.w), make_float2(b.z, b.w), acc);
    return acc;
}

__device__ __forceinline__ uint32_t smem_u32(const void* p) {
    uint32_t a;
    asm("{ .reg .u64 t; cvta.to.shared.u64 t, %1; cvt.u32.u64 %0, t; }" : "=r"(a) : "l"(p));
    return a;
}
__device__ __forceinline__ void ldsm4(uint32_t* a, uint32_t addr) {
    asm volatile("ldmatrix.sync.aligned.m8n8.x4.shared.b16 {%0,%1,%2,%3}, [%4];"
        : "=r"(a[0]), "=r"(a[1]), "=r"(a[2]), "=r"(a[3]) : "r"(addr));
}
__device__ __forceinline__ void mma16816(float* c, const uint32_t* a, const uint32_t* b) {
    asm volatile("mma.sync.aligned.m16n8k16.row.col.f32.bf16.bf16.f32 "
        "{%0,%1,%2,%3}, {%4,%5,%6,%7}, {%8,%9}, {%0,%1,%2,%3};"
        : "+f"(c[0]), "+f"(c[1]), "+f"(c[2]), "+f"(c[3])
        : "r"(a[0]), "r"(a[1]), "r"(a[2]), "r"(a[3]), "r"(b[0]), "r"(b[1]));
}
#define SWZ(x) ((x) ^ (((x) >> 3) & 0x70))

__device__ __forceinline__ __nv_bfloat162 split_hi(float a, float b) {
    __nv_bfloat162 h; h.x = __float2bfloat16(a); h.y = __float2bfloat16(b); return h;
}
__device__ __forceinline__ __nv_bfloat162 split_lo(float a, float b, __nv_bfloat162 h) {
    __nv_bfloat162 l;
    l.x = __float2bfloat16(a - __bfloat162float(h.x));
    l.y = __float2bfloat16(b - __bfloat162float(h.y));
    return l;
}
__device__ __forceinline__ uint32_t bf2u(__nv_bfloat162 v) {
    return *reinterpret_cast<uint32_t*>(&v);
}

// GRU tile-pair tables (kt-outer)
#define GRU_PNT {0,1,2,3,4,5,6,7,8,9,10,11, 0,1,2,3,4,5,6,7,8,9,10,11, 0,1,2,3,4,5,6,7,12,13,14,15}
#define GRU_PKT {0,0,0,0,0,0,0,0,0,0,0,0,  1,1,1,1,1,1,1,1,1,1,1,1,   2,2,2,2,2,2,2,2,2,2,2,2}

// ================= GRU B matrix value =================
__device__ __forceinline__ float gru_bval(
    int k, int n, const float* Whh, const float* Wih, const float* encW, int KIN)
{
    int blk = n >> 5, j = n & 31;
    if (k < 32) {
        if (blk == 3) return 0.f;
        return Whh[(blk * 32 + j) * 32 + k];
    }
    int f = k - 32;
    if (f >= KIN || blk == 2) return 0.f;
    int row = (blk == 3) ? 64 + j : blk * 32 + j;
    float s = 0.f;
    #pragma unroll
    for (int m = 0; m < 32; m++) s = fmaf(Wih[row * 32 + m], encW[m * KIN + f], s);
    return s;
}

// ====== merged weight prepack: MLP B-fragments + GRU B-fragments/biases =====
__global__ void k_packw(
    const float* __restrict__ W0, const float* __restrict__ W1,
    const float* __restrict__ aWih, const float* __restrict__ aWhh,
    const float* __restrict__ abih, const float* __restrict__ abhh,
    const float* __restrict__ eAW,  const float* __restrict__ eAb,
    const float* __restrict__ mWih, const float* __restrict__ mWhh,
    const float* __restrict__ mbih, const float* __restrict__ mbhh,
    const float* __restrict__ eMW,  const float* __restrict__ eMb)
{
    int tid = blockIdx.x * 256 + threadIdx.x;
    int lane = tid & 31, tq = lane & 3, g = lane >> 2;
    if (tid < 8192) {                       // W0 fragments
        int q = tid >> 5;
        int part = q & 1; q >>= 1;
        int ntg = q & 31;
        int k16 = q >> 5;
        int n = ntg * 8 + g;
        uint32_t rr[2];
        #pragma unroll
        for (int r = 0; r < 2; r++) {
            int k0 = k16 * 16 + tq * 2 + r * 8;
            float v0 = W0[n * 64 + k0], v1 = W0[n * 64 + k0 + 1];
            __nv_bfloat162 hh = split_hi(v0, v1);
            if (part == 0) rr[r] = bf2u(hh);
            else           rr[r] = bf2u(split_lo(v0, v1, hh));
        }
        g_W0f[tid] = make_uint2(rr[0], rr[1]);
    } else if (tid < 40960) {               // W1 fragments
        int j = tid - 8192;
        int q = j >> 5;
        int part = q & 1; q >>= 1;
        int ntg = q & 31;
        int ck = q >> 5;
        int n = ntg * 8 + g;
        uint32_t rr[2];
        #pragma unroll
        for (int r = 0; r < 2; r++) {
            int k0 = ck * 16 + tq * 2 + r * 8;
            float v0 = W1[n * 256 + k0], v1 = W1[n * 256 + k0 + 1];
            __nv_bfloat162 hh = split_hi(v0, v1);
            if (part == 0) rr[r] = bf2u(hh);
            else           rr[r] = bf2u(split_lo(v0, v1, hh));
        }
        g_W1f[j] = make_uint2(rr[0], rr[1]);
    } else if (tid < 40960 + 2304) {        // GRU B fragments
        const int PNT[36] = GRU_PNT;
        const int PKT[36] = GRU_PKT;
        int u = tid - 40960;
        int p = (u >> 5) % 36;
        int ty = u / (36 * 32);
        const float* Whh = ty ? mWhh : aWhh;
        const float* Wih = ty ? mWih : aWih;
        const float* eW  = ty ? eMW  : eAW;
        int KIN = ty ? 4 : 7;
        int n = PNT[p] * 8 + g;
        uint32_t rh[2], rl[2];
        #pragma unroll
        for (int r = 0; r < 2; r++) {
            int k0 = PKT[p] * 16 + tq * 2 + r * 8;
            float v0 = gru_bval(k0,     n, Whh, Wih, eW, KIN);
            float v1 = gru_bval(k0 + 1, n, Whh, Wih, eW, KIN);
            __nv_bfloat162 hh = split_hi(v0, v1);
            __nv_bfloat162 ll = split_lo(v0, v1, hh);
            rh[r] = bf2u(hh); rl[r] = bf2u(ll);
        }
        int base = (ty * 72 + p * 2) * 32 + lane;
        g_gB[base]      = make_uint2(rh[0], rh[1]);
        g_gB[base + 32] = make_uint2(rl[0], rl[1]);
    } else if (tid < 40960 + 2304 + 256) {  // GRU biases
        int u = tid - 40960 - 2304;
        int ty = u >> 7, n = u & 127;
        const float* Wih = ty ? mWih : aWih;
        const float* bih = ty ? mbih : abih;
        const float* bhh = ty ? mbhh : abhh;
        const float* eB  = ty ? eMb  : eAb;
        int blk = n >> 5, j = n & 31;
        float b;
        if (blk == 2) {
            b = bhh[64 + j];
        } else {
            int row = (blk == 3) ? 64 + j : blk * 32 + j;
            float bc = bih[row];
            #pragma unroll
            for (int m = 0; m < 32; m++) bc = fmaf(Wih[row * 32 + m], eB[m], bc);
            b = (blk < 2) ? bc + bhh[row] : bc;
        }
        g_gBias[ty * 128 + n] = b;
    }
}

// X A-fragment prepack (unchanged)
__global__ void k_packg_x(const float* __restrict__ obs) {
    int tid = blockIdx.x * 256 + threadIdx.x;
    int lane = tid & 31;
    int s = tid >> 5;
    int t = s & 127;
    int gr = s >> 7;
    int g = lane >> 2, tq = lane & 3;

    int KIN, xoff;
    int b0;
    if (gr < 128) { KIN = 7; xoff = 8; b0 = gr * 16; }
    else {
        int gi = gr - 128;
        KIN = 4;
        xoff = (gi < 128) ? 0 : 4;
        b0 = (gi < 128) ? gi * 16 : (gi - 128) * 16;
    }
    uint32_t hr[4], lr[4];
    #pragma unroll
    for (int r = 0; r < 4; r++) {
        int row = g + 8 * (r & 1);
        int k0 = tq * 2 + (r >> 1) * 8;
        float v0 = 0.f, v1 = 0.f;
        if (k0 < KIN)
            v0 = obs[(size_t)(b0 + row) * Tq * 15 + t * 15 + xoff + k0];
        if (k0 + 1 < KIN)
            v1 = obs[(size_t)(b0 + row) * Tq * 15 + t * 15 + xoff + k0 + 1];
        __nv_bfloat162 hh = split_hi(v0, v1);
        __nv_bfloat162 ll = split_lo(v0, v1, hh);
        hr[r] = bf2u(hh); lr[r] = bf2u(ll);
    }
    size_t idx = ((size_t)(gr * 128 + t) * 32 + lane) * 2;
    g_gX[idx]     = make_uint4(hr[0], hr[1], hr[2], hr[3]);
    g_gX[idx + 1] = make_uint4(lr[0], lr[1], lr[2], lr[3]);
}

// ====== GRU: tensor-core recurrence (R10 version, verbatim) ======
__global__ void __launch_bounds__(32) k_gru_tc(
    const float* __restrict__ rnn, float* __restrict__ next_h)
{
    const int PNT[36] = GRU_PNT;
    const int PKT[36] = GRU_PKT;
    int lane = threadIdx.x & 31;
    int w = blockIdx.x;
    int g = lane >> 2, tq = lane & 3;

    int ty; float* featb; int ib; bool is_air = (w < 128);
    if (is_air) { ty = 0; featb = g_air; ib = w * 16; }
    else {
        ty = 1;
        int gi = w - 128;
        if (gi < 128) { featb = g_m1; ib = gi * 16; }
        else          { featb = g_m2; ib = (gi - 128) * 16; }
    }
    int gi = w - 128;

    float hv[4][4];
    #pragma unroll
    for (int nt = 0; nt < 4; nt++) {
        int col = nt * 8 + 2 * tq;
        #pragma unroll
        for (int rh = 0; rh < 2; rh++) {
            int row = g + 8 * rh;
            const float* src;
            if (is_air) src = rnn + (size_t)(w * 16 + row) * 96 + col;
            else {
                int i = gi * 16 + row;
                src = rnn + (size_t)(i >> 1) * 96 + 32 + 32 * (i & 1) + col;
            }
            float2 v = *(const float2*)src;
            hv[nt][rh * 2]     = v.x;
            hv[nt][rh * 2 + 1] = v.y;
        }
    }
    float bias[16][2];
    #pragma unroll
    for (int nt = 0; nt < 16; nt++) {
        float2 v = *(const float2*)(g_gBias + ty * 128 + nt * 8 + 2 * tq);
        bias[nt][0] = v.x; bias[nt][1] = v.y;
    }
    uint32_t Ah[2][4], Al[2][4];
    #pragma unroll
    for (int nt = 0; nt < 4; nt++) {
        int kt = nt >> 1;
        __nv_bfloat162 h01 = split_hi(hv[nt][0], hv[nt][1]);
        __nv_bfloat162 l01 = split_lo(hv[nt][0], hv[nt][1], h01);
        __nv_bfloat162 h23 = split_hi(hv[nt][2], hv[nt][3]);
        __nv_bfloat162 l23 = split_lo(hv[nt][2], hv[nt][3], h23);
        int o = (nt & 1) ? 2 : 0;
        Ah[kt][o] = bf2u(h01); Ah[kt][o + 1] = bf2u(h23);
        Al[kt][o] = bf2u(l01); Al[kt][o + 1] = bf2u(l23);
    }

    const uint2* gBb = g_gB + ty * 72 * 32 + lane;
    const uint4* gXb = g_gX + ((size_t)w * 128) * 32 * 2 + lane * 2;
    float* fr0 = featb + (size_t)(ib + g)     * Tq * 32 + 2 * tq;
    float* fr1 = featb + (size_t)(ib + g + 8) * Tq * 32 + 2 * tq;

    uint4 xh_cur = gXb[0], xl_cur = gXb[1];

    #pragma unroll 1
    for (int t = 0; t < Tq; t++) {
        int tn = (t + 1 < Tq) ? t + 1 : t;
        uint4 xh_nxt = gXb[(size_t)tn * 64];
        uint4 xl_nxt = gXb[(size_t)tn * 64 + 1];

        uint32_t Xh[4] = {xh_cur.x, xh_cur.y, xh_cur.z, xh_cur.w};
        uint32_t Xl[4] = {xl_cur.x, xl_cur.y, xl_cur.z, xl_cur.w};
        float C[16][4];
        #pragma unroll
        for (int nt = 0; nt < 16; nt++) {
            C[nt][0] = bias[nt][0]; C[nt][1] = bias[nt][1];
            C[nt][2] = bias[nt][0]; C[nt][3] = bias[nt][1];
        }
        #pragma unroll
        for (int p = 0; p < 36; p++) {
            int nt = PNT[p], kt = PKT[p];
            uint2 bh = gBb[(p * 2) * 32];
            uint2 bl = gBb[(p * 2 + 1) * 32];
            const uint32_t* ah = (kt == 2) ? Xh : Ah[kt];
            const uint32_t* al = (kt == 2) ? Xl : Al[kt];
            mma16816(C[nt], ah, (const uint32_t*)&bh);
            mma16816(C[nt], ah, (const uint32_t*)&bl);
            mma16816(C[nt], al, (const uint32_t*)&bh);
        }
        #pragma unroll
        for (int nt = 0; nt < 4; nt++) {
            #pragma unroll
            for (int j = 0; j < 4; j++) {
                float r = fsig(C[nt][j]);
                float z = fsig(C[nt + 4][j]);
                float n = tanhap(fmaf(r, C[nt + 8][j], C[nt + 12][j]));
                hv[nt][j] = n + z * (hv[nt][j] - n);
            }
            *(float2*)(fr0 + (size_t)t * 32 + nt * 8) = make_float2(hv[nt][0], hv[nt][1]);
            *(float2*)(fr1 + (size_t)t * 32 + nt * 8) = make_float2(hv[nt][2], hv[nt][3]);
            int kt = nt >> 1;
            __nv_bfloat162 h01 = split_hi(hv[nt][0], hv[nt][1]);
            __nv_bfloat162 l01 = split_lo(hv[nt][0], hv[nt][1], h01);
            __nv_bfloat162 h23 = split_hi(hv[nt][2], hv[nt][3]);
            __nv_bfloat162 l23 = split_lo(hv[nt][2], hv[nt][3], h23);
            int o = (nt & 1) ? 2 : 0;
            Ah[kt][o] = bf2u(h01); Ah[kt][o + 1] = bf2u(h23);
            Al[kt][o] = bf2u(l01); Al[kt][o + 1] = bf2u(l23);
        }
        xh_cur = xh_nxt; xl_cur = xl_nxt;
    }
    #pragma unroll
    for (int nt = 0; nt < 4; nt++) {
        int col = nt * 8 + 2 * tq;
        #pragma unroll
        for (int rh = 0; rh < 2; rh++) {
            int row = g + 8 * rh;
            float2 v = make_float2(hv[nt][rh * 2], hv[nt][rh * 2 + 1]);
            float* dst;
            if (is_air) dst = next_h + (size_t)(w * 16 + row) * 96 + col;
            else {
                int i = gi * 16 + row;
                dst = next_h + (size_t)(i >> 1) * 96 + 32 + 32 * (i & 1) + col;
            }
            *(float2*)dst = v;
        }
    }
}

// ====== attention: reordered live ranges, 2 CTAs/SM ======
__global__ void __launch_bounds__(256, 2) k_attn(
    const float* __restrict__ obs,
    const float* __restrict__ Win, const float* __restrict__ bin,
    const float* __restrict__ Wout, const float* __restrict__ bout)
{
    __shared__ float Ws[96 * 32];
    __shared__ float Wo[32 * 32];
    __shared__ float bs[96], bo[32];
    int t = threadIdx.x;
    for (int i = t; i < 96 * 32; i += 256) Ws[i] = Win[i];
    for (int i = t; i < 32 * 32; i += 256) Wo[i] = Wout[i];
    if (t < 96) bs[t] = bin[t];
    if (t < 32) bo[t] = bout[t];
    __syncthreads();

    int warp = blockIdx.x * 8 + (t >> 5);
    int la = t & 31;
    int n = warp * 32 + la;
    float4* fr = (float4*)(g_fusion + (size_t)n * 64);

    // masks
    const float* op = obs + (size_t)n * 15;
    float o0=op[0],o1=op[1],o2=op[2],o3=op[3],o4=op[4],o5=op[5],o6=op[6],o7=op[7];
    const float T1 = 1.001e-5f, T0 = 1e-8f;
    bool mk0 = (fabsf(o0-1.f)<=T1) && (fabsf(o1)<=T0) && (fabsf(o2-1.f)<=T1) && (fabsf(o3)<=T0);
    bool mk1 = (fabsf(o4-1.f)<=T1) && (fabsf(o5)<=T0) && (fabsf(o6-1.f)<=T1) && (fabsf(o7)<=T0);

    // ---- phase 1: A resident, compute q, store air half, A dies ----
    float q[32];
    {
        float4 A[8];
        const float4* ap = (const float4*)(g_air + (size_t)n * 32);
        #pragma unroll
        for (int i = 0; i < 8; i++) A[i] = ap[i];
        #pragma unroll
        for (int c = 0; c < 32; c++) {
            float2 a = make_float2(bs[c], 0.f);
            const float4* w = (const float4*)(Ws + c * 32);
            #pragma unroll
            for (int k = 0; k < 8; k++) a = dot4_2(A[k], w[k], a);
            q[c] = a.x + a.y;
        }
        #pragma unroll
        for (int i = 0; i < 8; i++) fr[i] = A[i];
    }

    // ---- phase 2: M1/M2 resident, scores -> softmax -> ctx, M dies ----
    float ctx[32];
    bool allm = mk0 && mk1;
    {
        float4 M1[8], M2[8];
        const float4* p1 = (const float4*)(g_m1 + (size_t)n * 32);
        const float4* p2 = (const float4*)(g_m2 + (size_t)n * 32);
        #pragma unroll
        for (int i = 0; i < 8; i++) { M1[i] = p1[i]; M2[i] = p2[i]; }

        float s1[2] = {0.f, 0.f}, s2[2] = {0.f, 0.f};
        #pragma unroll
        for (int c = 0; c < 32; c++) {
            const float4* w = (const float4*)(Ws + (32 + c) * 32);
            float2 k1 = make_float2(bs[32 + c], 0.f), k2 = make_float2(0.f, 0.f);
            #pragma unroll
            for (int k = 0; k < 8; k++) { k1 = dot4_2(M1[k], w[k], k1); k2 = dot4_2(M2[k], w[k], k2); }
            int hh = c >> 4;
            s1[hh] = fmaf(q[c], k1.x + k1.y, s1[hh]);
            s2[hh] = fmaf(q[c], k2.x + k2.y + bs[32 + c], s2[hh]);
        }
        float w1[2], w2[2];
        #pragma unroll
        for (int hh = 0; hh < 2; hh++) {
            float a = s1[hh] * 0.25f + (mk0 ? -1e9f : 0.f);
            float b = s2[hh] * 0.25f + (mk1 ? -1e9f : 0.f);
            float m = fmaxf(a, b);
            float e1 = __expf(a - m), e2 = __expf(b - m);
            float inv = __fdividef(1.0f, e1 + e2);
            w1[hh] = e1 * inv; w2[hh] = e2 * inv;
        }
        #pragma unroll
        for (int c = 0; c < 32; c++) {
            const float4* w = (const float4*)(Ws + (64 + c) * 32);
            float2 v1 = make_float2(bs[64 + c], 0.f), v2 = make_float2(0.f, 0.f);
            #pragma unroll
            for (int k = 0; k < 8; k++) { v1 = dot4_2(M1[k], w[k], v1); v2 = dot4_2(M2[k], w[k], v2); }
            int hh = c >> 4;
            ctx[c] = w1[hh] * (v1.x + v1.y) + w2[hh] * (v2.x + v2.y + bs[64 + c]);
        }
    }

    // ---- phase 3: output proj in 8-col chunks, immediate stores ----
    #pragma unroll
    for (int ch = 0; ch < 4; ch++) {
        float at[8];
        #pragma unroll
        for (int oi = 0; oi < 8; oi++) {
            int o = ch * 8 + oi;
            float2 a = make_float2(bo[o], 0.f);
            const float4* w = (const float4*)(Wo + o * 32);
            #pragma unroll
            for (int c4 = 0; c4 < 8; c4++) {
                float4 cv = make_float4(ctx[4*c4], ctx[4*c4+1], ctx[4*c4+2], ctx[4*c4+3]);
                a = dot4_2(cv, w[c4], a);
            }
            at[oi] = allm ? 0.0f : (a.x + a.y);
        }
        fr[8 + ch * 2]     = make_float4(at[0], at[1], at[2], at[3]);
        fr[8 + ch * 2 + 1] = make_float4(at[4], at[5], at[6], at[7]);
    }
}

// ======= HMMA MLP: B from global fragments (R13 verbatim) ===
#define SM_B0  0
#define SM_B1  1024
#define SM_OW  2048
#define SM_A1H 3072
#define SM_A1L 36864
#define SM_RED 70656
#define SM_TOT 72704
#define SM_A0H 3072
#define SM_A0L 11264
#define PA1 528

__global__ void __launch_bounds__(256, 2) k_mlp_h(
    const float* __restrict__ b0, const float* __restrict__ b1,
    const float* __restrict__ oW, const float* __restrict__ ob,
    float* __restrict__ val)
{
    extern __shared__ char smem[];
    uint32_t smb = smem_u32(smem);
    int tid = threadIdx.x, wid = tid >> 5, lane = tid & 31;
    int g = lane >> 2, tq = lane & 3;
    int row0 = blockIdx.x * 64;

    float* b0s = (float*)(smem + SM_B0);
    float* b1s = (float*)(smem + SM_B1);
    float* ows = (float*)(smem + SM_OW);
    b0s[tid] = b0[tid]; b1s[tid] = b1[tid]; ows[tid] = oW[tid];

    int aro = lane & 15;
    int aco = (lane >> 1) & 8;

    {
        const float4* Fg = (const float4*)g_fusion + (size_t)row0 * 16;
        #pragma unroll
        for (int q = 0; q < 4; q++) {
            int id = tid + 256 * q;
            int r = id >> 4, c4 = id & 15;
            float4 v = Fg[id];
            __nv_bfloat162 h0 = split_hi(v.x, v.y), l0 = split_lo(v.x, v.y, h0);
            __nv_bfloat162 h1 = split_hi(v.z, v.w), l1 = split_lo(v.z, v.w, h1);
            uint32_t o0 = SWZ((uint32_t)(r * 128 + c4 * 8));
            uint32_t o1 = SWZ((uint32_t)(r * 128 + c4 * 8 + 4));
            *(__nv_bfloat162*)(smem + SM_A0H + o0) = h0;
            *(__nv_bfloat162*)(smem + SM_A0H + o1) = h1;
            *(__nv_bfloat162*)(smem + SM_A0L + o0) = l0;
            *(__nv_bfloat162*)(smem + SM_A0L + o1) = l1;
        }
    }
    __syncthreads();

    float acc[4][4][4];
    #pragma unroll
    for (int m = 0; m < 4; m++)
        #pragma unroll
        for (int nt = 0; nt < 4; nt++)
            #pragma unroll
            for (int r = 0; r < 4; r++) acc[m][nt][r] = 0.f;
    #pragma unroll 1
    for (int k16 = 0; k16 < 4; k16++) {
        uint2 bh[4], bl[4];
        #pragma unroll
        for (int nt = 0; nt < 4; nt++) {
            int f = ((k16 * 32 + wid * 4 + nt) * 2) * 32 + lane;
            bh[nt] = g_W0f[f];
            bl[nt] = g_W0f[f + 32];
        }
        #pragma unroll
        for (int m = 0; m < 4; m++) {
            uint32_t ah[4], al[4];
            uint32_t aa = SWZ((uint32_t)((m * 16 + aro) * 128 + (k16 * 16 + aco) * 2));
            ldsm4(ah, smb + SM_A0H + aa);
            ldsm4(al, smb + SM_A0L + aa);
            #pragma unroll
            for (int nt = 0; nt < 4; nt++) {
                mma16816(acc[m][nt], ah, (const uint32_t*)&bh[nt]);
                mma16816(acc[m][nt], ah, (const uint32_t*)&bl[nt]);
                mma16816(acc[m][nt], al, (const uint32_t*)&bh[nt]);
            }
        }
    }
    __syncthreads();

    #pragma unroll
    for (int m = 0; m < 4; m++)
        #pragma unroll
        for (int nt = 0; nt < 4; nt++) {
            int c0 = wid * 32 + 8 * nt + 2 * tq;
            float v0 = acc[m][nt][0] + b0s[c0];
            float v1 = acc[m][nt][1] + b0s[c0 + 1];
            float v2 = acc[m][nt][2] + b0s[c0];
            float v3 = acc[m][nt][3] + b0s[c0 + 1];
            v0 = v0 > 0.f ? v0 : 0.01f * v0;
            v1 = v1 > 0.f ? v1 : 0.01f * v1;
            v2 = v2 > 0.f ? v2 : 0.01f * v2;
            v3 = v3 > 0.f ? v3 : 0.01f * v3;
            int r0 = 16 * m + g, r1 = r0 + 8;
            __nv_bfloat162 h01 = split_hi(v0, v1), l01 = split_lo(v0, v1, h01);
            __nv_bfloat162 h23 = split_hi(v2, v3), l23 = split_lo(v2, v3, h23);
            *(__nv_bfloat162*)(smem + SM_A1H + r0 * PA1 + c0 * 2) = h01;
            *(__nv_bfloat162*)(smem + SM_A1L + r0 * PA1 + c0 * 2) = l01;
            *(__nv_bfloat162*)(smem + SM_A1H + r1 * PA1 + c0 * 2) = h23;
            *(__nv_bfloat162*)(smem + SM_A1L + r1 * PA1 + c0 * 2) = l23;
        }
    __syncthreads();

    float a2[4][4][4];
    #pragma unroll
    for (int m = 0; m < 4; m++)
        #pragma unroll
        for (int nt = 0; nt < 4; nt++)
            #pragma unroll
            for (int r = 0; r < 4; r++) a2[m][nt][r] = 0.f;
    #pragma unroll 1
    for (int c = 0; c < 8; c++) {
        #pragma unroll
        for (int k16 = 0; k16 < 2; k16++) {
            uint2 bh[4], bl[4];
            #pragma unroll
            for (int nt = 0; nt < 4; nt++) {
                int f = (((c * 2 + k16) * 32 + wid * 4 + nt) * 2) * 32 + lane;
                bh[nt] = g_W1f[f];
                bl[nt] = g_W1f[f + 32];
            }
            #pragma unroll
            for (int m = 0; m < 4; m++) {
                uint32_t ah[4], al[4];
                uint32_t aa = (uint32_t)((m * 16 + aro) * PA1 + (c * 32 + k16 * 16 + aco) * 2);
                ldsm4(ah, smb + SM_A1H + aa);
                ldsm4(al, smb + SM_A1L + aa);
                #pragma unroll
                for (int nt = 0; nt < 4; nt++) {
                    mma16816(a2[m][nt], ah, (const uint32_t*)&bh[nt]);
                    mma16816(a2[m][nt], ah, (const uint32_t*)&bl[nt]);
                    mma16816(a2[m][nt], al, (const uint32_t*)&bh[nt]);
                }
            }
        }
    }

    float* red = (float*)(smem + SM_RED);
    float p[4][2];
    #pragma unroll
    for (int m = 0; m < 4; m++) { p[m][0] = 0.f; p[m][1] = 0.f; }
    #pragma unroll
    for (int m = 0; m < 4; m++)
        #pragma unroll
        for (int nt = 0; nt < 4; nt++) {
            int c0 = wid * 32 + 8 * nt + 2 * tq;
            float w0v = ows[c0], w1v = ows[c0 + 1];
            float bb0 = b1s[c0], bb1 = b1s[c0 + 1];
            float v0 = a2[m][nt][0] + bb0;
            float v1 = a2[m][nt][1] + bb1;
            float v2 = a2[m][nt][2] + bb0;
            float v3 = a2[m][nt][3] + bb1;
            v0 = v0 > 0.f ? v0 : 0.01f * v0;
            v1 = v1 > 0.f ? v1 : 0.01f * v1;
            v2 = v2 > 0.f ? v2 : 0.01f * v2;
            v3 = v3 > 0.f ? v3 : 0.01f * v3;
            p[m][0] = fmaf(v0, w0v, p[m][0]);
            p[m][0] = fmaf(v1, w1v, p[m][0]);
            p[m][1] = fmaf(v2, w0v, p[m][1]);
            p[m][1] = fmaf(v3, w1v, p[m][1]);
        }
    #pragma unroll
    for (int off = 1; off <= 2; off <<= 1)
        #pragma unroll
        for (int m = 0; m < 4; m++) {
            p[m][0] += __shfl_xor_sync(0xffffffffu, p[m][0], off);
            p[m][1] += __shfl_xor_sync(0xffffffffu, p[m][1], off);
        }
    if (tq == 0) {
        #pragma unroll
        for (int m = 0; m < 4; m++) {
            red[wid * 64 + 16 * m + g]     = p[m][0];
            red[wid * 64 + 16 * m + g + 8] = p[m][1];
        }
    }
    __syncthreads();
    if (tid < 64) {
        float s = __ldg(ob);
        #pragma unroll
        for (int w8 = 0; w8 < 8; w8++) s += red[w8 * 64 + tid];
        val[row0 + tid] = s;
    }
}

extern "C" void kernel_launch(void* const* d_in, const int* in_sizes, int n_in,
                              void* d_out, int out_size) {
    const float* obs   = (const float*)d_in[0];
    const float* rnn   = (const float*)d_in[1];
    const float* eAW   = (const float*)d_in[2];
    const float* eAb   = (const float*)d_in[3];
    const float* eMW   = (const float*)d_in[4];
    const float* eMb   = (const float*)d_in[5];
    const float* aWih  = (const float*)d_in[6];
    const float* aWhh  = (const float*)d_in[7];
    const float* abih  = (const float*)d_in[8];
    const float* abhh  = (const float*)d_in[9];
    const float* mWih  = (const float*)d_in[10];
    const float* mWhh  = (const float*)d_in[11];
    const float* mbih  = (const float*)d_in[12];
    const float* mbhh  = (const float*)d_in[13];
    const float* Win   = (const float*)d_in[14];
    const float* bin   = (const float*)d_in[15];
    const float* Wout  = (const float*)d_in[16];
    const float* bout  = (const float*)d_in[17];
    const float* W0    = (const float*)d_in[18];
    const float* b0    = (const float*)d_in[19];
    const float* W1    = (const float*)d_in[20];
    const float* b1    = (const float*)d_in[21];
    const float* oW    = (const float*)d_in[22];
    const float* ob    = (const float*)d_in[23];

    float* out_val = (float*)d_out;
    float* out_h   = (float*)d_out + Nq;

    k_packw<<<170, 256>>>(W0, W1, aWih, aWhh, abih, abhh, eAW, eAb,
                          mWih, mWhh, mbih, mbhh, eMW, eMb);
    k_packg_x<<<6144, 256>>>(obs);
    k_gru_tc<<<384, 32>>>(rnn, out_h);
    k_attn<<<Nq / 32 / 8, 256>>>(obs, Win, bin, Wout, bout);
    cudaFuncSetAttribute(k_mlp_h, cudaFuncAttributeMaxDynamicSharedMemorySize, SM_TOT);
    k_mlp_h<<<Nq / 64, 256, SM_TOT>>>(b0, b1, oW, ob, out_val);
}

// round 15
// speedup vs baseline: 1.1767x; 1.1767x over previous
#include <cuda_runtime.h>
#include <cuda_bf16.h>
#include <cstdint>

#define Bq 2048
#define Tq 128
#define Nq (Bq*Tq)

// ---------------- scratch (no allocations allowed) ----------------
__device__ float g_air[(size_t)Nq * 32];
__device__ float g_m1 [(size_t)Nq * 32];
__device__ float g_m2 [(size_t)Nq * 32];
__device__ float g_attn[(size_t)Nq * 32];
// MLP weights prepacked in mma B-fragment layout (hi/lo split-bf16)
__device__ uint2 g_W0f[8192];
__device__ uint2 g_W1f[32768];
// attention weights as B-fragments: [mat(4)][kt(2)][nt(4)][part(2)][lane(32)]
__device__ uint2 g_Waf[2048];
// GRU tensor-core prepack
__device__ uint2  g_gB[2 * 36 * 2 * 32];
__device__ float  g_gBias[2 * 128];
__device__ uint4  g_gX[(size_t)384 * 128 * 32 * 2];

__device__ __forceinline__ float tanhap(float x) {
    float y;
    asm("tanh.approx.f32 %0, %1;" : "=f"(y) : "f"(x));
    return y;
}
__device__ __forceinline__ float fsig(float x) {
    return fmaf(0.5f, tanhap(0.5f * x), 0.5f);
}

__device__ __forceinline__ uint32_t smem_u32(const void* p) {
    uint32_t a;
    asm("{ .reg .u64 t; cvta.to.shared.u64 t, %1; cvt.u32.u64 %0, t; }" : "=r"(a) : "l"(p));
    return a;
}
__device__ __forceinline__ void ldsm4(uint32_t* a, uint32_t addr) {
    asm volatile("ldmatrix.sync.aligned.m8n8.x4.shared.b16 {%0,%1,%2,%3}, [%4];"
        : "=r"(a[0]), "=r"(a[1]), "=r"(a[2]), "=r"(a[3]) : "r"(addr));
}
__device__ __forceinline__ void mma16816(float* c, const uint32_t* a, const uint32_t* b) {
    asm volatile("mma.sync.aligned.m16n8k16.row.col.f32.bf16.bf16.f32 "
        "{%0,%1,%2,%3}, {%4,%5,%6,%7}, {%8,%9}, {%0,%1,%2,%3};"
        : "+f"(c[0]), "+f"(c[1]), "+f"(c[2]), "+f"(c[3])
        : "r"(a[0]), "r"(a[1]), "r"(a[2]), "r"(a[3]), "r"(b[0]), "r"(b[1]));
}
#define SWZ(x) ((x) ^ (((x) >> 3) & 0x70))

__device__ __forceinline__ __nv_bfloat162 split_hi(float a, float b) {
    __nv_bfloat162 h; h.x = __float2bfloat16(a); h.y = __float2bfloat16(b); return h;
}
__device__ __forceinline__ __nv_bfloat162 split_lo(float a, float b, __nv_bfloat162 h) {
    __nv_bfloat162 l;
    l.x = __float2bfloat16(a - __bfloat162float(h.x));
    l.y = __float2bfloat16(b - __bfloat162float(h.y));
    return l;
}
__device__ __forceinline__ uint32_t bf2u(__nv_bfloat162 v) {
    return *reinterpret_cast<uint32_t*>(&v);
}
__device__ __forceinline__ void split2(float a, float b, uint32_t& hi, uint32_t& lo) {
    __nv_bfloat162 h = split_hi(a, b);
    __nv_bfloat162 l = split_lo(a, b, h);
    hi = bf2u(h); lo = bf2u(l);
}

// GRU tile-pair tables (kt-outer)
#define GRU_PNT {0,1,2,3,4,5,6,7,8,9,10,11, 0,1,2,3,4,5,6,7,8,9,10,11, 0,1,2,3,4,5,6,7,12,13,14,15}
#define GRU_PKT {0,0,0,0,0,0,0,0,0,0,0,0,  1,1,1,1,1,1,1,1,1,1,1,1,   2,2,2,2,2,2,2,2,2,2,2,2}

__device__ __forceinline__ float gru_bval(
    int k, int n, const float* Whh, const float* Wih, const float* encW, int KIN)
{
    int blk = n >> 5, j = n & 31;
    if (k < 32) {
        if (blk == 3) return 0.f;
        return Whh[(blk * 32 + j) * 32 + k];
    }
    int f = k - 32;
    if (f >= KIN || blk == 2) return 0.f;
    int row = (blk == 3) ? 64 + j : blk * 32 + j;
    float s = 0.f;
    #pragma unroll
    for (int m = 0; m < 32; m++) s = fmaf(Wih[row * 32 + m], encW[m * KIN + f], s);
    return s;
}

// ====== merged weight prepack =====
__global__ void k_packw(
    const float* __restrict__ W0, const float* __restrict__ W1,
    const float* __restrict__ aWih, const float* __restrict__ aWhh,
    const float* __restrict__ abih, const float* __restrict__ abhh,
    const float* __restrict__ eAW,  const float* __restrict__ eAb,
    const float* __restrict__ mWih, const float* __restrict__ mWhh,
    const float* __restrict__ mbih, const float* __restrict__ mbhh,
    const float* __restrict__ eMW,  const float* __restrict__ eMb,
    const float* __restrict__ Win,  const float* __restrict__ Wout)
{
    int tid = blockIdx.x * 256 + threadIdx.x;
    int lane = tid & 31, tq = lane & 3, g = lane >> 2;
    if (tid < 8192) {                       // W0 fragments
        int q = tid >> 5;
        int part = q & 1; q >>= 1;
        int ntg = q & 31;
        int k16 = q >> 5;
        int n = ntg * 8 + g;
        uint32_t rr[2];
        #pragma unroll
        for (int r = 0; r < 2; r++) {
            int k0 = k16 * 16 + tq * 2 + r * 8;
            float v0 = W0[n * 64 + k0], v1 = W0[n * 64 + k0 + 1];
            __nv_bfloat162 hh = split_hi(v0, v1);
            if (part == 0) rr[r] = bf2u(hh);
            else           rr[r] = bf2u(split_lo(v0, v1, hh));
        }
        g_W0f[tid] = make_uint2(rr[0], rr[1]);
    } else if (tid < 40960) {               // W1 fragments
        int j = tid - 8192;
        int q = j >> 5;
        int part = q & 1; q >>= 1;
        int ntg = q & 31;
        int ck = q >> 5;
        int n = ntg * 8 + g;
        uint32_t rr[2];
        #pragma unroll
        for (int r = 0; r < 2; r++) {
            int k0 = ck * 16 + tq * 2 + r * 8;
            float v0 = W1[n * 256 + k0], v1 = W1[n * 256 + k0 + 1];
            __nv_bfloat162 hh = split_hi(v0, v1);
            if (part == 0) rr[r] = bf2u(hh);
            else           rr[r] = bf2u(split_lo(v0, v1, hh));
        }
        g_W1f[j] = make_uint2(rr[0], rr[1]);
    } else if (tid < 40960 + 2304) {        // GRU B fragments
        const int PNT[36] = GRU_PNT;
        const int PKT[36] = GRU_PKT;
        int u = tid - 40960;
        int p = (u >> 5) % 36;
        int ty = u / (36 * 32);
        const float* Whh = ty ? mWhh : aWhh;
        const float* Wih = ty ? mWih : aWih;
        const float* eW  = ty ? eMW  : eAW;
        int KIN = ty ? 4 : 7;
        int n = PNT[p] * 8 + g;
        uint32_t rh[2], rl[2];
        #pragma unroll
        for (int r = 0; r < 2; r++) {
            int k0 = PKT[p] * 16 + tq * 2 + r * 8;
            float v0 = gru_bval(k0,     n, Whh, Wih, eW, KIN);
            float v1 = gru_bval(k0 + 1, n, Whh, Wih, eW, KIN);
            __nv_bfloat162 hh = split_hi(v0, v1);
            __nv_bfloat162 ll = split_lo(v0, v1, hh);
            rh[r] = bf2u(hh); rl[r] = bf2u(ll);
        }
        int base = (ty * 72 + p * 2) * 32 + lane;
        g_gB[base]      = make_uint2(rh[0], rh[1]);
        g_gB[base + 32] = make_uint2(rl[0], rl[1]);
    } else if (tid < 40960 + 2304 + 256) {  // GRU biases
        int u = tid - 40960 - 2304;
        int ty = u >> 7, n = u & 127;
        const float* Wih = ty ? mWih : aWih;
        const float* bih = ty ? mbih : abih;
        const float* bhh = ty ? mbhh : abhh;
        const float* eB  = ty ? eMb  : eAb;
        int blk = n >> 5, j = n & 31;
        float b;
        if (blk == 2) {
            b = bhh[64 + j];
        } else {
            int row = (blk == 3) ? 64 + j : blk * 32 + j;
            float bc = bih[row];
            #pragma unroll
            for (int m = 0; m < 32; m++) bc = fmaf(Wih[row * 32 + m], eB[m], bc);
            b = (blk < 2) ? bc + bhh[row] : bc;
        }
        g_gBias[ty * 128 + n] = b;
    } else if (tid < 40960 + 2304 + 256 + 2048) {   // attention B fragments
        int u = tid - 40960 - 2304 - 256;
        int q = u >> 5;
        int part = q & 1; q >>= 1;
        int nt = q & 3; q >>= 2;
        int kt = q & 1;
        int m = q >> 1;                     // 0=Wq 1=Wk 2=Wv 3=Wo
        int n = nt * 8 + g;
        const float* M = (m < 3) ? (Win + (m * 32 + n) * 32) : (Wout + n * 32);
        uint32_t rr[2];
        #pragma unroll
        for (int r = 0; r < 2; r++) {
            int k0 = kt * 16 + tq * 2 + r * 8;
            float v0 = M[k0], v1 = M[k0 + 1];
            __nv_bfloat162 hh = split_hi(v0, v1);
            if (part == 0) rr[r] = bf2u(hh);
            else           rr[r] = bf2u(split_lo(v0, v1, hh));
        }
        g_Waf[((m * 2 + kt) * 4 + nt) * 64 + part * 32 + lane] = make_uint2(rr[0], rr[1]);
    }
}

// X A-fragment prepack (unchanged)
__global__ void k_packg_x(const float* __restrict__ obs) {
    int tid = blockIdx.x * 256 + threadIdx.x;
    int lane = tid & 31;
    int s = tid >> 5;
    int t = s & 127;
    int gr = s >> 7;
    int g = lane >> 2, tq = lane & 3;

    int KIN, xoff;
    int b0;
    if (gr < 128) { KIN = 7; xoff = 8; b0 = gr * 16; }
    else {
        int gi = gr - 128;
        KIN = 4;
        xoff = (gi < 128) ? 0 : 4;
        b0 = (gi < 128) ? gi * 16 : (gi - 128) * 16;
    }
    uint32_t hr[4], lr[4];
    #pragma unroll
    for (int r = 0; r < 4; r++) {
        int row = g + 8 * (r & 1);
        int k0 = tq * 2 + (r >> 1) * 8;
        float v0 = 0.f, v1 = 0.f;
        if (k0 < KIN)
            v0 = obs[(size_t)(b0 + row) * Tq * 15 + t * 15 + xoff + k0];
        if (k0 + 1 < KIN)
            v1 = obs[(size_t)(b0 + row) * Tq * 15 + t * 15 + xoff + k0 + 1];
        split2(v0, v1, hr[r], lr[r]);
    }
    size_t idx = ((size_t)(gr * 128 + t) * 32 + lane) * 2;
    g_gX[idx]     = make_uint4(hr[0], hr[1], hr[2], hr[3]);
    g_gX[idx + 1] = make_uint4(lr[0], lr[1], lr[2], lr[3]);
}

// ====== GRU: tensor-core recurrence (R10 version, verbatim) ======
__global__ void __launch_bounds__(32) k_gru_tc(
    const float* __restrict__ rnn, float* __restrict__ next_h)
{
    const int PNT[36] = GRU_PNT;
    const int PKT[36] = GRU_PKT;
    int lane = threadIdx.x & 31;
    int w = blockIdx.x;
    int g = lane >> 2, tq = lane & 3;

    int ty; float* featb; int ib; bool is_air = (w < 128);
    if (is_air) { ty = 0; featb = g_air; ib = w * 16; }
    else {
        ty = 1;
        int gi = w - 128;
        if (gi < 128) { featb = g_m1; ib = gi * 16; }
        else          { featb = g_m2; ib = (gi - 128) * 16; }
    }
    int gi = w - 128;

    float hv[4][4];
    #pragma unroll
    for (int nt = 0; nt < 4; nt++) {
        int col = nt * 8 + 2 * tq;
        #pragma unroll
        for (int rh = 0; rh < 2; rh++) {
            int row = g + 8 * rh;
            const float* src;
            if (is_air) src = rnn + (size_t)(w * 16 + row) * 96 + col;
            else {
                int i = gi * 16 + row;
                src = rnn + (size_t)(i >> 1) * 96 + 32 + 32 * (i & 1) + col;
            }
            float2 v = *(const float2*)src;
            hv[nt][rh * 2]     = v.x;
            hv[nt][rh * 2 + 1] = v.y;
        }
    }
    float bias[16][2];
    #pragma unroll
    for (int nt = 0; nt < 16; nt++) {
        float2 v = *(const float2*)(g_gBias + ty * 128 + nt * 8 + 2 * tq);
        bias[nt][0] = v.x; bias[nt][1] = v.y;
    }
    uint32_t Ah[2][4], Al[2][4];
    #pragma unroll
    for (int nt = 0; nt < 4; nt++) {
        int kt = nt >> 1;
        int o = (nt & 1) ? 2 : 0;
        split2(hv[nt][0], hv[nt][1], Ah[kt][o],     Al[kt][o]);
        split2(hv[nt][2], hv[nt][3], Ah[kt][o + 1], Al[kt][o + 1]);
    }

    const uint2* gBb = g_gB + ty * 72 * 32 + lane;
    const uint4* gXb = g_gX + ((size_t)w * 128) * 32 * 2 + lane * 2;
    float* fr0 = featb + (size_t)(ib + g)     * Tq * 32 + 2 * tq;
    float* fr1 = featb + (size_t)(ib + g + 8) * Tq * 32 + 2 * tq;

    uint4 xh_cur = gXb[0], xl_cur = gXb[1];

    #pragma unroll 1
    for (int t = 0; t < Tq; t++) {
        int tn = (t + 1 < Tq) ? t + 1 : t;
        uint4 xh_nxt = gXb[(size_t)tn * 64];
        uint4 xl_nxt = gXb[(size_t)tn * 64 + 1];

        uint32_t Xh[4] = {xh_cur.x, xh_cur.y, xh_cur.z, xh_cur.w};
        uint32_t Xl[4] = {xl_cur.x, xl_cur.y, xl_cur.z, xl_cur.w};
        float C[16][4];
        #pragma unroll
        for (int nt = 0; nt < 16; nt++) {
            C[nt][0] = bias[nt][0]; C[nt][1] = bias[nt][1];
            C[nt][2] = bias[nt][0]; C[nt][3] = bias[nt][1];
        }
        #pragma unroll
        for (int p = 0; p < 36; p++) {
            int nt = PNT[p], kt = PKT[p];
            uint2 bh = gBb[(p * 2) * 32];
            uint2 bl = gBb[(p * 2 + 1) * 32];
            const uint32_t* ah = (kt == 2) ? Xh : Ah[kt];
            const uint32_t* al = (kt == 2) ? Xl : Al[kt];
            mma16816(C[nt], ah, (const uint32_t*)&bh);
            mma16816(C[nt], ah, (const uint32_t*)&bl);
            mma16816(C[nt], al, (const uint32_t*)&bh);
        }
        #pragma unroll
        for (int nt = 0; nt < 4; nt++) {
            #pragma unroll
            for (int j = 0; j < 4; j++) {
                float r = fsig(C[nt][j]);
                float z = fsig(C[nt + 4][j]);
                float n = tanhap(fmaf(r, C[nt + 8][j], C[nt + 12][j]));
                hv[nt][j] = n + z * (hv[nt][j] - n);
            }
            *(float2*)(fr0 + (size_t)t * 32 + nt * 8) = make_float2(hv[nt][0], hv[nt][1]);
            *(float2*)(fr1 + (size_t)t * 32 + nt * 8) = make_float2(hv[nt][2], hv[nt][3]);
            int kt = nt >> 1;
            int o = (nt & 1) ? 2 : 0;
            split2(hv[nt][0], hv[nt][1], Ah[kt][o],     Al[kt][o]);
            split2(hv[nt][2], hv[nt][3], Ah[kt][o + 1], Al[kt][o + 1]);
        }
        xh_cur = xh_nxt; xl_cur = xl_nxt;
    }
    #pragma unroll
    for (int nt = 0; nt < 4; nt++) {
        int col = nt * 8 + 2 * tq;
        #pragma unroll
        for (int rh = 0; rh < 2; rh++) {
            int row = g + 8 * rh;
            float2 v = make_float2(hv[nt][rh * 2], hv[nt][rh * 2 + 1]);
            float* dst;
            if (is_air) dst = next_h + (size_t)(w * 16 + row) * 96 + col;
            else {
                int i = gi * 16 + row;
                dst = next_h + (size_t)(i >> 1) * 96 + 32 + 32 * (i & 1) + col;
            }
            *(float2*)dst = v;
        }
    }
}

// ====== attention: tensor-core, warp = 16 rows ======
__device__ __forceinline__ void load_frag(const float* base, int ra, int rb, int tq,
                                          uint32_t Ah[2][4], uint32_t Al[2][4]) {
    #pragma unroll
    for (int kt = 0; kt < 2; kt++) {
        float2 a0 = *(const float2*)(base + (size_t)ra * 32 + kt * 16 + 2 * tq);
        float2 b0 = *(const float2*)(base + (size_t)rb * 32 + kt * 16 + 2 * tq);
        float2 a2 = *(const float2*)(base + (size_t)ra * 32 + kt * 16 + 2 * tq + 8);
        float2 b2 = *(const float2*)(base + (size_t)rb * 32 + kt * 16 + 2 * tq + 8);
        split2(a0.x, a0.y, Ah[kt][0], Al[kt][0]);
        split2(b0.x, b0.y, Ah[kt][1], Al[kt][1]);
        split2(a2.x, a2.y, Ah[kt][2], Al[kt][2]);
        split2(b2.x, b2.y, Ah[kt][3], Al[kt][3]);
    }
}
__device__ __forceinline__ void attn_gemm(float C[4][4], const uint32_t Ah[2][4],
                                          const uint32_t Al[2][4], int mat, int lane) {
    #pragma unroll
    for (int nt = 0; nt < 4; nt++) {
        C[nt][0] = 0.f; C[nt][1] = 0.f; C[nt][2] = 0.f; C[nt][3] = 0.f;
    }
    #pragma unroll
    for (int kt = 0; kt < 2; kt++)
        #pragma unroll
        for (int nt = 0; nt < 4; nt++) {
            int base = ((mat * 2 + kt) * 4 + nt) * 64 + lane;
            uint2 bh = g_Waf[base];
            uint2 bl = g_Waf[base + 32];
            mma16816(C[nt], Ah[kt], (const uint32_t*)&bh);
            mma16816(C[nt], Ah[kt], (const uint32_t*)&bl);
            mma16816(C[nt], Al[kt], (const uint32_t*)&bh);
        }
}

__global__ void __launch_bounds__(256) k_attn_tc(
    const float* __restrict__ obs,
    const float* __restrict__ bin, const float* __restrict__ bout)
{
    int lane = threadIdx.x & 31, wid = threadIdx.x >> 5;
    int wg = blockIdx.x * 8 + wid;
    int r0 = wg * 16;
    int g = lane >> 2, tq = lane & 3;
    int ra = r0 + g, rb = r0 + g + 8;

    // masks for rows ra, rb
    const float T1 = 1.001e-5f, T0 = 1e-8f;
    bool mk0a, mk1a, mk0b, mk1b;
    {
        const float* oa = obs + (size_t)ra * 15;
        const float* ob_ = obs + (size_t)rb * 15;
        mk0a = (fabsf(oa[0]-1.f)<=T1)&&(fabsf(oa[1])<=T0)&&(fabsf(oa[2]-1.f)<=T1)&&(fabsf(oa[3])<=T0);
        mk1a = (fabsf(oa[4]-1.f)<=T1)&&(fabsf(oa[5])<=T0)&&(fabsf(oa[6]-1.f)<=T1)&&(fabsf(oa[7])<=T0);
        mk0b = (fabsf(ob_[0]-1.f)<=T1)&&(fabsf(ob_[1])<=T0)&&(fabsf(ob_[2]-1.f)<=T1)&&(fabsf(ob_[3])<=T0);
        mk1b = (fabsf(ob_[4]-1.f)<=T1)&&(fabsf(ob_[5])<=T0)&&(fabsf(ob_[6]-1.f)<=T1)&&(fabsf(ob_[7])<=T0);
    }
    // biases for this lane's columns (col = nt*8 + 2tq, +1)
    float2 bq[4], bk[4], bv[4], bo2[4];
    #pragma unroll
    for (int nt = 0; nt < 4; nt++) {
        int col = nt * 8 + 2 * tq;
        bq[nt]  = *(const float2*)(bin + col);
        bk[nt]  = *(const float2*)(bin + 32 + col);
        bv[nt]  = *(const float2*)(bin + 64 + col);
        bo2[nt] = *(const float2*)(bout + col);
    }

    // q = air @ Wq^T + bq
    float q[4][4];
    {
        uint32_t Ah[2][4], Al[2][4];
        load_frag(g_air, ra, rb, tq, Ah, Al);
        attn_gemm(q, Ah, Al, 0, lane);
    }
    #pragma unroll
    for (int nt = 0; nt < 4; nt++) {
        q[nt][0] += bq[nt].x; q[nt][1] += bq[nt].y;
        q[nt][2] += bq[nt].x; q[nt][3] += bq[nt].y;
    }

    // k1/v1 from m1, k2/v2 from m2
    float k1[4][4], v1[4][4], k2[4][4], v2[4][4];
    {
        uint32_t Ah[2][4], Al[2][4];
        load_frag(g_m1, ra, rb, tq, Ah, Al);
        attn_gemm(k1, Ah, Al, 1, lane);
        attn_gemm(v1, Ah, Al, 2, lane);
        load_frag(g_m2, ra, rb, tq, Ah, Al);
        attn_gemm(k2, Ah, Al, 1, lane);
        attn_gemm(v2, Ah, Al, 2, lane);
    }
    #pragma unroll
    for (int nt = 0; nt < 4; nt++) {
        k1[nt][0] += bk[nt].x; k1[nt][1] += bk[nt].y; k1[nt][2] += bk[nt].x; k1[nt][3] += bk[nt].y;
        k2[nt][0] += bk[nt].x; k2[nt][1] += bk[nt].y; k2[nt][2] += bk[nt].x; k2[nt][3] += bk[nt].y;
        v1[nt][0] += bv[nt].x; v1[nt][1] += bv[nt].y; v1[nt][2] += bv[nt].x; v1[nt][3] += bv[nt].y;
        v2[nt][0] += bv[nt].x; v2[nt][1] += bv[nt].y; v2[nt][2] += bv[nt].x; v2[nt][3] += bv[nt].y;
    }

    // scores: s[h][row] partial over this lane's cols, reduced over the 4 tq lanes
    float s1[2][2], s2[2][2];
    #pragma unroll
    for (int h = 0; h < 2; h++)
        #pragma unroll
        for (int rj = 0; rj < 2; rj++) {
            int jb = rj * 2;
            float t1 = 0.f, t2 = 0.f;
            #pragma unroll
            for (int u = 0; u < 2; u++) {
                int nt = 2 * h + u;
                t1 += q[nt][jb] * k1[nt][jb] + q[nt][jb+1] * k1[nt][jb+1];
                t2 += q[nt][jb] * k2[nt][jb] + q[nt][jb+1] * k2[nt][jb+1];
            }
            s1[h][rj] = t1; s2[h][rj] = t2;
        }
    #pragma unroll
    for (int off = 1; off <= 2; off <<= 1)
        #pragma unroll
        for (int h = 0; h < 2; h++)
            #pragma unroll
            for (int rj = 0; rj < 2; rj++) {
                s1[h][rj] += __shfl_xor_sync(0xffffffffu, s1[h][rj], off);
                s2[h][rj] += __shfl_xor_sync(0xffffffffu, s2[h][rj], off);
            }

    // softmax per (head, row)
    float w1[2][2], w2[2][2];
    #pragma unroll
    for (int rj = 0; rj < 2; rj++) {
        bool mk0 = rj ? mk0b : mk0a;
        bool mk1 = rj ? mk1b : mk1a;
        #pragma unroll
        for (int h = 0; h < 2; h++) {
            float a = s1[h][rj] * 0.25f + (mk0 ? -1e9f : 0.f);
            float b = s2[h][rj] * 0.25f + (mk1 ? -1e9f : 0.f);
            float m = fmaxf(a, b);
            float e1 = __expf(a - m), e2 = __expf(b - m);
            float inv = __fdividef(1.0f, e1 + e2);
            w1[h][rj] = e1 * inv; w2[h][rj] = e2 * inv;
        }
    }

    // ctx in C layout, then re-pack to A fragments (same renaming as GRU)
    uint32_t Ch[2][4], Cl[2][4];
    #pragma unroll
    for (int nt = 0; nt < 4; nt++) {
        int h = nt >> 1;
        float c0 = w1[h][0] * v1[nt][0] + w2[h][0] * v2[nt][0];
        float c1 = w1[h][0] * v1[nt][1] + w2[h][0] * v2[nt][1];
        float c2 = w1[h][1] * v1[nt][2] + w2[h][1] * v2[nt][2];
        float c3 = w1[h][1] * v1[nt][3] + w2[h][1] * v2[nt][3];
        int kt = nt >> 1;
        int o = (nt & 1) ? 2 : 0;
        split2(c0, c1, Ch[kt][o],     Cl[kt][o]);
        split2(c2, c3, Ch[kt][o + 1], Cl[kt][o + 1]);
    }

    // out = ctx @ Wout^T + bo; zero rows where both masked
    float out[4][4];
    attn_gemm(out, Ch, Cl, 3, lane);
    bool za = mk0a && mk1a, zb = mk0b && mk1b;
    #pragma unroll
    for (int nt = 0; nt < 4; nt++) {
        float o0 = za ? 0.f : (out[nt][0] + bo2[nt].x);
        float o1 = za ? 0.f : (out[nt][1] + bo2[nt].y);
        float o2 = zb ? 0.f : (out[nt][2] + bo2[nt].x);
        float o3 = zb ? 0.f : (out[nt][3] + bo2[nt].y);
        *(float2*)(g_attn + (size_t)ra * 32 + nt * 8 + 2 * tq) = make_float2(o0, o1);
        *(float2*)(g_attn + (size_t)rb * 32 + nt * 8 + 2 * tq) = make_float2(o2, o3);
    }
}

// ======= HMMA MLP: B from global fragments; fusion = [g_air | g_attn] ===
#define SM_B0  0
#define SM_B1  1024
#define SM_OW  2048
#define SM_A1H 3072
#define SM_A1L 36864
#define SM_RED 70656
#define SM_TOT 72704
#define SM_A0H 3072
#define SM_A0L 11264
#define PA1 528

__global__ void __launch_bounds__(256, 2) k_mlp_h(
    const float* __restrict__ b0, const float* __restrict__ b1,
    const float* __restrict__ oW, const float* __restrict__ ob,
    float* __restrict__ val)
{
    extern __shared__ char smem[];
    uint32_t smb = smem_u32(smem);
    int tid = threadIdx.x, wid = tid >> 5, lane = tid & 31;
    int g = lane >> 2, tq = lane & 3;
    int row0 = blockIdx.x * 64;

    float* b0s = (float*)(smem + SM_B0);
    float* b1s = (float*)(smem + SM_B1);
    float* ows = (float*)(smem + SM_OW);
    b0s[tid] = b0[tid]; b1s[tid] = b1[tid]; ows[tid] = oW[tid];

    int aro = lane & 15;
    int aco = (lane >> 1) & 8;

    {
        #pragma unroll
        for (int q = 0; q < 4; q++) {
            int id = tid + 256 * q;
            int r = id >> 4, c4 = id & 15;
            const float4* src = (c4 < 8)
                ? (const float4*)(g_air  + (size_t)(row0 + r) * 32) + c4
                : (const float4*)(g_attn + (size_t)(row0 + r) * 32) + (c4 - 8);
            float4 v = *src;
            __nv_bfloat162 h0 = split_hi(v.x, v.y), l0 = split_lo(v.x, v.y, h0);
            __nv_bfloat162 h1 = split_hi(v.z, v.w), l1 = split_lo(v.z, v.w, h1);
            uint32_t o0 = SWZ((uint32_t)(r * 128 + c4 * 8));
            uint32_t o1 = SWZ((uint32_t)(r * 128 + c4 * 8 + 4));
            *(__nv_bfloat162*)(smem + SM_A0H + o0) = h0;
            *(__nv_bfloat162*)(smem + SM_A0H + o1) = h1;
            *(__nv_bfloat162*)(smem + SM_A0L + o0) = l0;
            *(__nv_bfloat162*)(smem + SM_A0L + o1) = l1;
        }
    }
    __syncthreads();

    float acc[4][4][4];
    #pragma unroll
    for (int m = 0; m < 4; m++)
        #pragma unroll
        for (int nt = 0; nt < 4; nt++)
            #pragma unroll
            for (int r = 0; r < 4; r++) acc[m][nt][r] = 0.f;
    #pragma unroll 1
    for (int k16 = 0; k16 < 4; k16++) {
        uint2 bh[4], bl[4];
        #pragma unroll
        for (int nt = 0; nt < 4; nt++) {
            int f = ((k16 * 32 + wid * 4 + nt) * 2) * 32 + lane;
            bh[nt] = g_W0f[f];
            bl[nt] = g_W0f[f + 32];
        }
        #pragma unroll
        for (int m = 0; m < 4; m++) {
            uint32_t ah[4], al[4];
            uint32_t aa = SWZ((uint32_t)((m * 16 + aro) * 128 + (k16 * 16 + aco) * 2));
            ldsm4(ah, smb + SM_A0H + aa);
            ldsm4(al, smb + SM_A0L + aa);
            #pragma unroll
            for (int nt = 0; nt < 4; nt++) {
                mma16816(acc[m][nt], ah, (const uint32_t*)&bh[nt]);
                mma16816(acc[m][nt], ah, (const uint32_t*)&bl[nt]);
                mma16816(acc[m][nt], al, (const uint32_t*)&bh[nt]);
            }
        }
    }
    __syncthreads();

    #pragma unroll
    for (int m = 0; m < 4; m++)
        #pragma unroll
        for (int nt = 0; nt < 4; nt++) {
            int c0 = wid * 32 + 8 * nt + 2 * tq;
            float v0 = acc[m][nt][0] + b0s[c0];
            float v1 = acc[m][nt][1] + b0s[c0 + 1];
            float v2 = acc[m][nt][2] + b0s[c0];
            float v3 = acc[m][nt][3] + b0s[c0 + 1];
            v0 = v0 > 0.f ? v0 : 0.01f * v0;
            v1 = v1 > 0.f ? v1 : 0.01f * v1;
            v2 = v2 > 0.f ? v2 : 0.01f * v2;
            v3 = v3 > 0.f ? v3 : 0.01f * v3;
            int r0 = 16 * m + g, r1 = r0 + 8;
            __nv_bfloat162 h01 = split_hi(v0, v1), l01 = split_lo(v0, v1, h01);
            __nv_bfloat162 h23 = split_hi(v2, v3), l23 = split_lo(v2, v3, h23);
            *(__nv_bfloat162*)(smem + SM_A1H + r0 * PA1 + c0 * 2) = h01;
            *(__nv_bfloat162*)(smem + SM_A1L + r0 * PA1 + c0 * 2) = l01;
            *(__nv_bfloat162*)(smem + SM_A1H + r1 * PA1 + c0 * 2) = h23;
            *(__nv_bfloat162*)(smem + SM_A1L + r1 * PA1 + c0 * 2) = l23;
        }
    __syncthreads();

    float a2[4][4][4];
    #pragma unroll
    for (int m = 0; m < 4; m++)
        #pragma unroll
        for (int nt = 0; nt < 4; nt++)
            #pragma unroll
            for (int r = 0; r < 4; r++) a2[m][nt][r] = 0.f;
    #pragma unroll 1
    for (int c = 0; c < 8; c++) {
        #pragma unroll
        for (int k16 = 0; k16 < 2; k16++) {
            uint2 bh[4], bl[4];
            #pragma unroll
            for (int nt = 0; nt < 4; nt++) {
                int f = (((c * 2 + k16) * 32 + wid * 4 + nt) * 2) * 32 + lane;
                bh[nt] = g_W1f[f];
                bl[nt] = g_W1f[f + 32];
            }
            #pragma unroll
            for (int m = 0; m < 4; m++) {
                uint32_t ah[4], al[4];
                uint32_t aa = (uint32_t)((m * 16 + aro) * PA1 + (c * 32 + k16 * 16 + aco) * 2);
                ldsm4(ah, smb + SM_A1H + aa);
                ldsm4(al, smb + SM_A1L + aa);
                #pragma unroll
                for (int nt = 0; nt < 4; nt++) {
                    mma16816(a2[m][nt], ah, (const uint32_t*)&bh[nt]);
                    mma16816(a2[m][nt], ah, (const uint32_t*)&bl[nt]);
                    mma16816(a2[m][nt], al, (const uint32_t*)&bh[nt]);
                }
            }
        }
    }

    float* red = (float*)(smem + SM_RED);
    float p[4][2];
    #pragma unroll
    for (int m = 0; m < 4; m++) { p[m][0] = 0.f; p[m][1] = 0.f; }
    #pragma unroll
    for (int m = 0; m < 4; m++)
        #pragma unroll
        for (int nt = 0; nt < 4; nt++) {
            int c0 = wid * 32 + 8 * nt + 2 * tq;
            float w0v = ows[c0], w1v = ows[c0 + 1];
            float bb0 = b1s[c0], bb1 = b1s[c0 + 1];
            float v0 = a2[m][nt][0] + bb0;
            float v1 = a2[m][nt][1] + bb1;
            float v2 = a2[m][nt][2] + bb0;
            float v3 = a2[m][nt][3] + bb1;
            v0 = v0 > 0.f ? v0 : 0.01f * v0;
            v1 = v1 > 0.f ? v1 : 0.01f * v1;
            v2 = v2 > 0.f ? v2 : 0.01f * v2;
            v3 = v3 > 0.f ? v3 : 0.01f * v3;
            p[m][0] = fmaf(v0, w0v, p[m][0]);
            p[m][0] = fmaf(v1, w1v, p[m][0]);
            p[m][1] = fmaf(v2, w0v, p[m][1]);
            p[m][1] = fmaf(v3, w1v, p[m][1]);
        }
    #pragma unroll
    for (int off = 1; off <= 2; off <<= 1)
        #pragma unroll
        for (int m = 0; m < 4; m++) {
            p[m][0] += __shfl_xor_sync(0xffffffffu, p[m][0], off);
            p[m][1] += __shfl_xor_sync(0xffffffffu, p[m][1], off);
        }
    if (tq == 0) {
        #pragma unroll
        for (int m = 0; m < 4; m++) {
            red[wid * 64 + 16 * m + g]     = p[m][0];
            red[wid * 64 + 16 * m + g + 8] = p[m][1];
        }
    }
    __syncthreads();
    if (tid < 64) {
        float s = __ldg(ob);
        #pragma unroll
        for (int w8 = 0; w8 < 8; w8++) s += red[w8 * 64 + tid];
        val[row0 + tid] = s;
    }
}

extern "C" void kernel_launch(void* const* d_in, const int* in_sizes, int n_in,
                              void* d_out, int out_size) {
    const float* obs   = (const float*)d_in[0];
    const float* rnn   = (const float*)d_in[1];
    const float* eAW   = (const float*)d_in[2];
    const float* eAb   = (const float*)d_in[3];
    const float* eMW   = (const float*)d_in[4];
    const float* eMb   = (const float*)d_in[5];
    const float* aWih  = (const float*)d_in[6];
    const float* aWhh  = (const float*)d_in[7];
    const float* abih  = (const float*)d_in[8];
    const float* abhh  = (const float*)d_in[9];
    const float* mWih  = (const float*)d_in[10];
    const float* mWhh  = (const float*)d_in[11];
    const float* mbih  = (const float*)d_in[12];
    const float* mbhh  = (const float*)d_in[13];
    const float* Win   = (const float*)d_in[14];
    const float* bin   = (const float*)d_in[15];
    const float* Wout  = (const float*)d_in[16];
    const float* bout  = (const float*)d_in[17];
    const float* W0    = (const float*)d_in[18];
    const float* b0    = (const float*)d_in[19];
    const float* W1    = (const float*)d_in[20];
    const float* b1    = (const float*)d_in[21];
    const float* oW    = (const float*)d_in[22];
    const float* ob    = (const float*)d_in[23];

    float* out_val = (float*)d_out;
    float* out_h   = (float*)d_out + Nq;

    k_packw<<<178, 256>>>(W0, W1, aWih, aWhh, abih, abhh, eAW, eAb,
                          mWih, mWhh, mbih, mbhh, eMW, eMb, Win, Wout);
    k_packg_x<<<6144, 256>>>(obs);
    k_gru_tc<<<384, 32>>>(rnn, out_h);
    k_attn_tc<<<Nq / 16 / 8, 256>>>(obs, bin, bout);
    cudaFuncSetAttribute(k_mlp_h, cudaFuncAttributeMaxDynamicSharedMemorySize, SM_TOT);
    k_mlp_h<<<Nq / 64, 256, SM_TOT>>>(b0, b1, oW, ob, out_val);
}

// round 16
// speedup vs baseline: 1.2215x; 1.0381x over previous
#include <cuda_runtime.h>
#include <cuda_bf16.h>
#include <cstdint>

#define Bq 2048
#define Tq 128
#define Nq (Bq*Tq)

// ---------------- scratch (no allocations allowed) ----------------
__device__ float g_air[(size_t)Nq * 32];
__device__ float g_m1 [(size_t)Nq * 32];
__device__ float g_m2 [(size_t)Nq * 32];
__device__ float g_attn[(size_t)Nq * 32];
// MLP weights prepacked in mma B-fragment layout (hi/lo split-bf16)
__device__ uint2 g_W0f[8192];
__device__ uint2 g_W1f[32768];
// attention weights as B-fragments: [mat(4)][kt(2)][nt(4)][part(2)][lane(32)]
__device__ uint2 g_Waf[2048];
// GRU tensor-core prepack
__device__ uint2  g_gB[2 * 36 * 2 * 32];
__device__ float  g_gBias[2 * 128];
// X fragments compressed: r2/r3 are structurally zero (KIN<8) -> one uint4
// per (group,t,lane) = {hi.r0, hi.r1, lo.r0, lo.r1}
__device__ uint4  g_gX[(size_t)384 * 128 * 32];

__device__ __forceinline__ float tanhap(float x) {
    float y;
    asm("tanh.approx.f32 %0, %1;" : "=f"(y) : "f"(x));
    return y;
}
__device__ __forceinline__ float fsig(float x) {
    return fmaf(0.5f, tanhap(0.5f * x), 0.5f);
}

__device__ __forceinline__ uint32_t smem_u32(const void* p) {
    uint32_t a;
    asm("{ .reg .u64 t; cvta.to.shared.u64 t, %1; cvt.u32.u64 %0, t; }" : "=r"(a) : "l"(p));
    return a;
}
__device__ __forceinline__ void ldsm4(uint32_t* a, uint32_t addr) {
    asm volatile("ldmatrix.sync.aligned.m8n8.x4.shared.b16 {%0,%1,%2,%3}, [%4];"
        : "=r"(a[0]), "=r"(a[1]), "=r"(a[2]), "=r"(a[3]) : "r"(addr));
}
__device__ __forceinline__ void mma16816(float* c, const uint32_t* a, const uint32_t* b) {
    asm volatile("mma.sync.aligned.m16n8k16.row.col.f32.bf16.bf16.f32 "
        "{%0,%1,%2,%3}, {%4,%5,%6,%7}, {%8,%9}, {%0,%1,%2,%3};"
        : "+f"(c[0]), "+f"(c[1]), "+f"(c[2]), "+f"(c[3])
        : "r"(a[0]), "r"(a[1]), "r"(a[2]), "r"(a[3]), "r"(b[0]), "r"(b[1]));
}
#define SWZ(x) ((x) ^ (((x) >> 3) & 0x70))

__device__ __forceinline__ __nv_bfloat162 split_hi(float a, float b) {
    __nv_bfloat162 h; h.x = __float2bfloat16(a); h.y = __float2bfloat16(b); return h;
}
__device__ __forceinline__ __nv_bfloat162 split_lo(float a, float b, __nv_bfloat162 h) {
    __nv_bfloat162 l;
    l.x = __float2bfloat16(a - __bfloat162float(h.x));
    l.y = __float2bfloat16(b - __bfloat162float(h.y));
    return l;
}
__device__ __forceinline__ uint32_t bf2u(__nv_bfloat162 v) {
    return *reinterpret_cast<uint32_t*>(&v);
}
__device__ __forceinline__ void split2(float a, float b, uint32_t& hi, uint32_t& lo) {
    __nv_bfloat162 h = split_hi(a, b);
    __nv_bfloat162 l = split_lo(a, b, h);
    hi = bf2u(h); lo = bf2u(l);
}

// GRU tile-pair tables (kt-outer)
#define GRU_PNT {0,1,2,3,4,5,6,7,8,9,10,11, 0,1,2,3,4,5,6,7,8,9,10,11, 0,1,2,3,4,5,6,7,12,13,14,15}
#define GRU_PKT {0,0,0,0,0,0,0,0,0,0,0,0,  1,1,1,1,1,1,1,1,1,1,1,1,   2,2,2,2,2,2,2,2,2,2,2,2}

__device__ __forceinline__ float gru_bval(
    int k, int n, const float* Whh, const float* Wih, const float* encW, int KIN)
{
    int blk = n >> 5, j = n & 31;
    if (k < 32) {
        if (blk == 3) return 0.f;
        return Whh[(blk * 32 + j) * 32 + k];
    }
    int f = k - 32;
    if (f >= KIN || blk == 2) return 0.f;
    int row = (blk == 3) ? 64 + j : blk * 32 + j;
    float s = 0.f;
    #pragma unroll
    for (int m = 0; m < 32; m++) s = fmaf(Wih[row * 32 + m], encW[m * KIN + f], s);
    return s;
}

// ====== merged weight prepack =====
__global__ void k_packw(
    const float* __restrict__ W0, const float* __restrict__ W1,
    const float* __restrict__ aWih, const float* __restrict__ aWhh,
    const float* __restrict__ abih, const float* __restrict__ abhh,
    const float* __restrict__ eAW,  const float* __restrict__ eAb,
    const float* __restrict__ mWih, const float* __restrict__ mWhh,
    const float* __restrict__ mbih, const float* __restrict__ mbhh,
    const float* __restrict__ eMW,  const float* __restrict__ eMb,
    const float* __restrict__ Win,  const float* __restrict__ Wout)
{
    int tid = blockIdx.x * 256 + threadIdx.x;
    int lane = tid & 31, tq = lane & 3, g = lane >> 2;
    if (tid < 8192) {                       // W0 fragments
        int q = tid >> 5;
        int part = q & 1; q >>= 1;
        int ntg = q & 31;
        int k16 = q >> 5;
        int n = ntg * 8 + g;
        uint32_t rr[2];
        #pragma unroll
        for (int r = 0; r < 2; r++) {
            int k0 = k16 * 16 + tq * 2 + r * 8;
            float v0 = W0[n * 64 + k0], v1 = W0[n * 64 + k0 + 1];
            __nv_bfloat162 hh = split_hi(v0, v1);
            if (part == 0) rr[r] = bf2u(hh);
            else           rr[r] = bf2u(split_lo(v0, v1, hh));
        }
        g_W0f[tid] = make_uint2(rr[0], rr[1]);
    } else if (tid < 40960) {               // W1 fragments
        int j = tid - 8192;
        int q = j >> 5;
        int part = q & 1; q >>= 1;
        int ntg = q & 31;
        int ck = q >> 5;
        int n = ntg * 8 + g;
        uint32_t rr[2];
        #pragma unroll
        for (int r = 0; r < 2; r++) {
            int k0 = ck * 16 + tq * 2 + r * 8;
            float v0 = W1[n * 256 + k0], v1 = W1[n * 256 + k0 + 1];
            __nv_bfloat162 hh = split_hi(v0, v1);
            if (part == 0) rr[r] = bf2u(hh);
            else           rr[r] = bf2u(split_lo(v0, v1, hh));
        }
        g_W1f[j] = make_uint2(rr[0], rr[1]);
    } else if (tid < 40960 + 2304) {        // GRU B fragments
        const int PNT[36] = GRU_PNT;
        const int PKT[36] = GRU_PKT;
        int u = tid - 40960;
        int p = (u >> 5) % 36;
        int ty = u / (36 * 32);
        const float* Whh = ty ? mWhh : aWhh;
        const float* Wih = ty ? mWih : aWih;
        const float* eW  = ty ? eMW  : eAW;
        int KIN = ty ? 4 : 7;
        int n = PNT[p] * 8 + g;
        uint32_t rh[2], rl[2];
        #pragma unroll
        for (int r = 0; r < 2; r++) {
            int k0 = PKT[p] * 16 + tq * 2 + r * 8;
            float v0 = gru_bval(k0,     n, Whh, Wih, eW, KIN);
            float v1 = gru_bval(k0 + 1, n, Whh, Wih, eW, KIN);
            __nv_bfloat162 hh = split_hi(v0, v1);
            __nv_bfloat162 ll = split_lo(v0, v1, hh);
            rh[r] = bf2u(hh); rl[r] = bf2u(ll);
        }
        int base = (ty * 72 + p * 2) * 32 + lane;
        g_gB[base]      = make_uint2(rh[0], rh[1]);
        g_gB[base + 32] = make_uint2(rl[0], rl[1]);
    } else if (tid < 40960 + 2304 + 256) {  // GRU biases
        int u = tid - 40960 - 2304;
        int ty = u >> 7, n = u & 127;
        const float* Wih = ty ? mWih : aWih;
        const float* bih = ty ? mbih : abih;
        const float* bhh = ty ? mbhh : abhh;
        const float* eB  = ty ? eMb  : eAb;
        int blk = n >> 5, j = n & 31;
        float b;
        if (blk == 2) {
            b = bhh[64 + j];
        } else {
            int row = (blk == 3) ? 64 + j : blk * 32 + j;
            float bc = bih[row];
            #pragma unroll
            for (int m = 0; m < 32; m++) bc = fmaf(Wih[row * 32 + m], eB[m], bc);
            b = (blk < 2) ? bc + bhh[row] : bc;
        }
        g_gBias[ty * 128 + n] = b;
    } else if (tid < 40960 + 2304 + 256 + 2048) {   // attention B fragments
        int u = tid - 40960 - 2304 - 256;
        int q = u >> 5;
        int part = q & 1; q >>= 1;
        int nt = q & 3; q >>= 2;
        int kt = q & 1;
        int m = q >> 1;                     // 0=Wq 1=Wk 2=Wv 3=Wo
        int n = nt * 8 + g;
        const float* M = (m < 3) ? (Win + (m * 32 + n) * 32) : (Wout + n * 32);
        uint32_t rr[2];
        #pragma unroll
        for (int r = 0; r < 2; r++) {
            int k0 = kt * 16 + tq * 2 + r * 8;
            float v0 = M[k0], v1 = M[k0 + 1];
            __nv_bfloat162 hh = split_hi(v0, v1);
            if (part == 0) rr[r] = bf2u(hh);
            else           rr[r] = bf2u(split_lo(v0, v1, hh));
        }
        g_Waf[((m * 2 + kt) * 4 + nt) * 64 + part * 32 + lane] = make_uint2(rr[0], rr[1]);
    }
}

// X A-fragment prepack (compressed: only r0/r1, hi+lo in one uint4)
__global__ void k_packg_x(const float* __restrict__ obs) {
    int tid = blockIdx.x * 256 + threadIdx.x;
    int lane = tid & 31;
    int s = tid >> 5;
    int t = s & 127;
    int gr = s >> 7;
    int g = lane >> 2, tq = lane & 3;

    int KIN, xoff;
    int b0;
    if (gr < 128) { KIN = 7; xoff = 8; b0 = gr * 16; }
    else {
        int gi = gr - 128;
        KIN = 4;
        xoff = (gi < 128) ? 0 : 4;
        b0 = (gi < 128) ? gi * 16 : (gi - 128) * 16;
    }
    uint32_t hr[2], lr[2];
    #pragma unroll
    for (int r = 0; r < 2; r++) {
        int row = g + 8 * r;
        int k0 = tq * 2;
        float v0 = 0.f, v1 = 0.f;
        if (k0 < KIN)
            v0 = obs[(size_t)(b0 + row) * Tq * 15 + t * 15 + xoff + k0];
        if (k0 + 1 < KIN)
            v1 = obs[(size_t)(b0 + row) * Tq * 15 + t * 15 + xoff + k0 + 1];
        split2(v0, v1, hr[r], lr[r]);
    }
    g_gX[(size_t)(gr * 128 + t) * 32 + lane] = make_uint4(hr[0], hr[1], lr[0], lr[1]);
}

// ====== GRU: tensor-core recurrence ======
__global__ void __launch_bounds__(32) k_gru_tc(
    const float* __restrict__ rnn, float* __restrict__ next_h)
{
    const int PNT[36] = GRU_PNT;
    const int PKT[36] = GRU_PKT;
    int lane = threadIdx.x & 31;
    int w = blockIdx.x;
    int g = lane >> 2, tq = lane & 3;

    int ty; float* featb; int ib; bool is_air = (w < 128);
    if (is_air) { ty = 0; featb = g_air; ib = w * 16; }
    else {
        ty = 1;
        int gi = w - 128;
        if (gi < 128) { featb = g_m1; ib = gi * 16; }
        else          { featb = g_m2; ib = (gi - 128) * 16; }
    }
    int gi = w - 128;

    float hv[4][4];
    #pragma unroll
    for (int nt = 0; nt < 4; nt++) {
        int col = nt * 8 + 2 * tq;
        #pragma unroll
        for (int rh = 0; rh < 2; rh++) {
            int row = g + 8 * rh;
            const float* src;
            if (is_air) src = rnn + (size_t)(w * 16 + row) * 96 + col;
            else {
                int i = gi * 16 + row;
                src = rnn + (size_t)(i >> 1) * 96 + 32 + 32 * (i & 1) + col;
            }
            float2 v = *(const float2*)src;
            hv[nt][rh * 2]     = v.x;
            hv[nt][rh * 2 + 1] = v.y;
        }
    }
    float bias[16][2];
    #pragma unroll
    for (int nt = 0; nt < 16; nt++) {
        float2 v = *(const float2*)(g_gBias + ty * 128 + nt * 8 + 2 * tq);
        bias[nt][0] = v.x; bias[nt][1] = v.y;
    }
    uint32_t Ah[2][4], Al[2][4];
    #pragma unroll
    for (int nt = 0; nt < 4; nt++) {
        int kt = nt >> 1;
        int o = (nt & 1) ? 2 : 0;
        split2(hv[nt][0], hv[nt][1], Ah[kt][o],     Al[kt][o]);
        split2(hv[nt][2], hv[nt][3], Ah[kt][o + 1], Al[kt][o + 1]);
    }

    const uint2* gBb = g_gB + ty * 72 * 32 + lane;
    const uint4* gXb = g_gX + (size_t)w * 128 * 32 + lane;
    float* fr0 = featb + (size_t)(ib + g)     * Tq * 32 + 2 * tq;
    float* fr1 = featb + (size_t)(ib + g + 8) * Tq * 32 + 2 * tq;

    uint4 x_cur = gXb[0];

    #pragma unroll 1
    for (int t = 0; t < Tq; t++) {
        int tn = (t + 1 < Tq) ? t + 1 : t;
        uint4 x_nxt = gXb[(size_t)tn * 32];

        uint32_t Xh[4] = {x_cur.x, x_cur.y, 0u, 0u};
        uint32_t Xl[4] = {x_cur.z, x_cur.w, 0u, 0u};
        float C[16][4];
        #pragma unroll
        for (int nt = 0; nt < 16; nt++) {
            C[nt][0] = bias[nt][0]; C[nt][1] = bias[nt][1];
            C[nt][2] = bias[nt][0]; C[nt][3] = bias[nt][1];
        }
        #pragma unroll
        for (int p = 0; p < 36; p++) {
            int nt = PNT[p], kt = PKT[p];
            uint2 bh = gBb[(p * 2) * 32];
            uint2 bl = gBb[(p * 2 + 1) * 32];
            const uint32_t* ah = (kt == 2) ? Xh : Ah[kt];
            const uint32_t* al = (kt == 2) ? Xl : Al[kt];
            mma16816(C[nt], ah, (const uint32_t*)&bh);
            mma16816(C[nt], ah, (const uint32_t*)&bl);
            mma16816(C[nt], al, (const uint32_t*)&bh);
        }
        #pragma unroll
        for (int nt = 0; nt < 4; nt++) {
            #pragma unroll
            for (int j = 0; j < 4; j++) {
                float r = fsig(C[nt][j]);
                float z = fsig(C[nt + 4][j]);
                float n = tanhap(fmaf(r, C[nt + 8][j], C[nt + 12][j]));
                hv[nt][j] = n + z * (hv[nt][j] - n);
            }
            *(float2*)(fr0 + (size_t)t * 32 + nt * 8) = make_float2(hv[nt][0], hv[nt][1]);
            *(float2*)(fr1 + (size_t)t * 32 + nt * 8) = make_float2(hv[nt][2], hv[nt][3]);
            int kt = nt >> 1;
            int o = (nt & 1) ? 2 : 0;
            split2(hv[nt][0], hv[nt][1], Ah[kt][o],     Al[kt][o]);
            split2(hv[nt][2], hv[nt][3], Ah[kt][o + 1], Al[kt][o + 1]);
        }
        x_cur = x_nxt;
    }
    #pragma unroll
    for (int nt = 0; nt < 4; nt++) {
        int col = nt * 8 + 2 * tq;
        #pragma unroll
        for (int rh = 0; rh < 2; rh++) {
            int row = g + 8 * rh;
            float2 v = make_float2(hv[nt][rh * 2], hv[nt][rh * 2 + 1]);
            float* dst;
            if (is_air) dst = next_h + (size_t)(w * 16 + row) * 96 + col;
            else {
                int i = gi * 16 + row;
                dst = next_h + (size_t)(i >> 1) * 96 + 32 + 32 * (i & 1) + col;
            }
            *(float2*)dst = v;
        }
    }
}

// ====== attention: tensor-core, warp = 16 rows (R15 verbatim) ======
__device__ __forceinline__ void load_frag(const float* base, int ra, int rb, int tq,
                                          uint32_t Ah[2][4], uint32_t Al[2][4]) {
    #pragma unroll
    for (int kt = 0; kt < 2; kt++) {
        float2 a0 = *(const float2*)(base + (size_t)ra * 32 + kt * 16 + 2 * tq);
        float2 b0 = *(const float2*)(base + (size_t)rb * 32 + kt * 16 + 2 * tq);
        float2 a2 = *(const float2*)(base + (size_t)ra * 32 + kt * 16 + 2 * tq + 8);
        float2 b2 = *(const float2*)(base + (size_t)rb * 32 + kt * 16 + 2 * tq + 8);
        split2(a0.x, a0.y, Ah[kt][0], Al[kt][0]);
        split2(b0.x, b0.y, Ah[kt][1], Al[kt][1]);
        split2(a2.x, a2.y, Ah[kt][2], Al[kt][2]);
        split2(b2.x, b2.y, Ah[kt][3], Al[kt][3]);
    }
}
__device__ __forceinline__ void attn_gemm(float C[4][4], const uint32_t Ah[2][4],
                                          const uint32_t Al[2][4], int mat, int lane) {
    #pragma unroll
    for (int nt = 0; nt < 4; nt++) {
        C[nt][0] = 0.f; C[nt][1] = 0.f; C[nt][2] = 0.f; C[nt][3] = 0.f;
    }
    #pragma unroll
    for (int kt = 0; kt < 2; kt++)
        #pragma unroll
        for (int nt = 0; nt < 4; nt++) {
            int base = ((mat * 2 + kt) * 4 + nt) * 64 + lane;
            uint2 bh = g_Waf[base];
            uint2 bl = g_Waf[base + 32];
            mma16816(C[nt], Ah[kt], (const uint32_t*)&bh);
            mma16816(C[nt], Ah[kt], (const uint32_t*)&bl);
            mma16816(C[nt], Al[kt], (const uint32_t*)&bh);
        }
}

__global__ void __launch_bounds__(256) k_attn_tc(
    const float* __restrict__ obs,
    const float* __restrict__ bin, const float* __restrict__ bout)
{
    int lane = threadIdx.x & 31, wid = threadIdx.x >> 5;
    int wg = blockIdx.x * 8 + wid;
    int r0 = wg * 16;
    int g = lane >> 2, tq = lane & 3;
    int ra = r0 + g, rb = r0 + g + 8;

    const float T1 = 1.001e-5f, T0 = 1e-8f;
    bool mk0a, mk1a, mk0b, mk1b;
    {
        const float* oa = obs + (size_t)ra * 15;
        const float* ob_ = obs + (size_t)rb * 15;
        mk0a = (fabsf(oa[0]-1.f)<=T1)&&(fabsf(oa[1])<=T0)&&(fabsf(oa[2]-1.f)<=T1)&&(fabsf(oa[3])<=T0);
        mk1a = (fabsf(oa[4]-1.f)<=T1)&&(fabsf(oa[5])<=T0)&&(fabsf(oa[6]-1.f)<=T1)&&(fabsf(oa[7])<=T0);
        mk0b = (fabsf(ob_[0]-1.f)<=T1)&&(fabsf(ob_[1])<=T0)&&(fabsf(ob_[2]-1.f)<=T1)&&(fabsf(ob_[3])<=T0);
        mk1b = (fabsf(ob_[4]-1.f)<=T1)&&(fabsf(ob_[5])<=T0)&&(fabsf(ob_[6]-1.f)<=T1)&&(fabsf(ob_[7])<=T0);
    }
    float2 bq[4], bk[4], bv[4], bo2[4];
    #pragma unroll
    for (int nt = 0; nt < 4; nt++) {
        int col = nt * 8 + 2 * tq;
        bq[nt]  = *(const float2*)(bin + col);
        bk[nt]  = *(const float2*)(bin + 32 + col);
        bv[nt]  = *(const float2*)(bin + 64 + col);
        bo2[nt] = *(const float2*)(bout + col);
    }

    float q[4][4];
    {
        uint32_t Ah[2][4], Al[2][4];
        load_frag(g_air, ra, rb, tq, Ah, Al);
        attn_gemm(q, Ah, Al, 0, lane);
    }
    #pragma unroll
    for (int nt = 0; nt < 4; nt++) {
        q[nt][0] += bq[nt].x; q[nt][1] += bq[nt].y;
        q[nt][2] += bq[nt].x; q[nt][3] += bq[nt].y;
    }

    float k1[4][4], v1[4][4], k2[4][4], v2[4][4];
    {
        uint32_t Ah[2][4], Al[2][4];
        load_frag(g_m1, ra, rb, tq, Ah, Al);
        attn_gemm(k1, Ah, Al, 1, lane);
        attn_gemm(v1, Ah, Al, 2, lane);
        load_frag(g_m2, ra, rb, tq, Ah, Al);
        attn_gemm(k2, Ah, Al, 1, lane);
        attn_gemm(v2, Ah, Al, 2, lane);
    }
    #pragma unroll
    for (int nt = 0; nt < 4; nt++) {
        k1[nt][0] += bk[nt].x; k1[nt][1] += bk[nt].y; k1[nt][2] += bk[nt].x; k1[nt][3] += bk[nt].y;
        k2[nt][0] += bk[nt].x; k2[nt][1] += bk[nt].y; k2[nt][2] += bk[nt].x; k2[nt][3] += bk[nt].y;
        v1[nt][0] += bv[nt].x; v1[nt][1] += bv[nt].y; v1[nt][2] += bv[nt].x; v1[nt][3] += bv[nt].y;
        v2[nt][0] += bv[nt].x; v2[nt][1] += bv[nt].y; v2[nt][2] += bv[nt].x; v2[nt][3] += bv[nt].y;
    }

    float s1[2][2], s2[2][2];
    #pragma unroll
    for (int h = 0; h < 2; h++)
        #pragma unroll
        for (int rj = 0; rj < 2; rj++) {
            int jb = rj * 2;
            float t1 = 0.f, t2 = 0.f;
            #pragma unroll
            for (int u = 0; u < 2; u++) {
                int nt = 2 * h + u;
                t1 += q[nt][jb] * k1[nt][jb] + q[nt][jb+1] * k1[nt][jb+1];
                t2 += q[nt][jb] * k2[nt][jb] + q[nt][jb+1] * k2[nt][jb+1];
            }
            s1[h][rj] = t1; s2[h][rj] = t2;
        }
    #pragma unroll
    for (int off = 1; off <= 2; off <<= 1)
        #pragma unroll
        for (int h = 0; h < 2; h++)
            #pragma unroll
            for (int rj = 0; rj < 2; rj++) {
                s1[h][rj] += __shfl_xor_sync(0xffffffffu, s1[h][rj], off);
                s2[h][rj] += __shfl_xor_sync(0xffffffffu, s2[h][rj], off);
            }

    float w1[2][2], w2[2][2];
    #pragma unroll
    for (int rj = 0; rj < 2; rj++) {
        bool mk0 = rj ? mk0b : mk0a;
        bool mk1 = rj ? mk1b : mk1a;
        #pragma unroll
        for (int h = 0; h < 2; h++) {
            float a = s1[h][rj] * 0.25f + (mk0 ? -1e9f : 0.f);
            float b = s2[h][rj] * 0.25f + (mk1 ? -1e9f : 0.f);
            float m = fmaxf(a, b);
            float e1 = __expf(a - m), e2 = __expf(b - m);
            float inv = __fdividef(1.0f, e1 + e2);
            w1[h][rj] = e1 * inv; w2[h][rj] = e2 * inv;
        }
    }

    uint32_t Ch[2][4], Cl[2][4];
    #pragma unroll
    for (int nt = 0; nt < 4; nt++) {
        int h = nt >> 1;
        float c0 = w1[h][0] * v1[nt][0] + w2[h][0] * v2[nt][0];
        float c1 = w1[h][0] * v1[nt][1] + w2[h][0] * v2[nt][1];
        float c2 = w1[h][1] * v1[nt][2] + w2[h][1] * v2[nt][2];
        float c3 = w1[h][1] * v1[nt][3] + w2[h][1] * v2[nt][3];
        int kt = nt >> 1;
        int o = (nt & 1) ? 2 : 0;
        split2(c0, c1, Ch[kt][o],     Cl[kt][o]);
        split2(c2, c3, Ch[kt][o + 1], Cl[kt][o + 1]);
    }

    float out[4][4];
    attn_gemm(out, Ch, Cl, 3, lane);
    bool za = mk0a && mk1a, zb = mk0b && mk1b;
    #pragma unroll
    for (int nt = 0; nt < 4; nt++) {
        float o0 = za ? 0.f : (out[nt][0] + bo2[nt].x);
        float o1 = za ? 0.f : (out[nt][1] + bo2[nt].y);
        float o2 = zb ? 0.f : (out[nt][2] + bo2[nt].x);
        float o3 = zb ? 0.f : (out[nt][3] + bo2[nt].y);
        *(float2*)(g_attn + (size_t)ra * 32 + nt * 8 + 2 * tq) = make_float2(o0, o1);
        *(float2*)(g_attn + (size_t)rb * 32 + nt * 8 + 2 * tq) = make_float2(o2, o3);
    }
}

// ======= HMMA MLP (R15 verbatim) ===
#define SM_B0  0
#define SM_B1  1024
#define SM_OW  2048
#define SM_A1H 3072
#define SM_A1L 36864
#define SM_RED 70656
#define SM_TOT 72704
#define SM_A0H 3072
#define SM_A0L 11264
#define PA1 528

__global__ void __launch_bounds__(256, 2) k_mlp_h(
    const float* __restrict__ b0, const float* __restrict__ b1,
    const float* __restrict__ oW, const float* __restrict__ ob,
    float* __restrict__ val)
{
    extern __shared__ char smem[];
    uint32_t smb = smem_u32(smem);
    int tid = threadIdx.x, wid = tid >> 5, lane = tid & 31;
    int g = lane >> 2, tq = lane & 3;
    int row0 = blockIdx.x * 64;

    float* b0s = (float*)(smem + SM_B0);
    float* b1s = (float*)(smem + SM_B1);
    float* ows = (float*)(smem + SM_OW);
    b0s[tid] = b0[tid]; b1s[tid] = b1[tid]; ows[tid] = oW[tid];

    int aro = lane & 15;
    int aco = (lane >> 1) & 8;

    {
        #pragma unroll
        for (int q = 0; q < 4; q++) {
            int id = tid + 256 * q;
            int r = id >> 4, c4 = id & 15;
            const float4* src = (c4 < 8)
                ? (const float4*)(g_air  + (size_t)(row0 + r) * 32) + c4
                : (const float4*)(g_attn + (size_t)(row0 + r) * 32) + (c4 - 8);
            float4 v = *src;
            __nv_bfloat162 h0 = split_hi(v.x, v.y), l0 = split_lo(v.x, v.y, h0);
            __nv_bfloat162 h1 = split_hi(v.z, v.w), l1 = split_lo(v.z, v.w, h1);
            uint32_t o0 = SWZ((uint32_t)(r * 128 + c4 * 8));
            uint32_t o1 = SWZ((uint32_t)(r * 128 + c4 * 8 + 4));
            *(__nv_bfloat162*)(smem + SM_A0H + o0) = h0;
            *(__nv_bfloat162*)(smem + SM_A0H + o1) = h1;
            *(__nv_bfloat162*)(smem + SM_A0L + o0) = l0;
            *(__nv_bfloat162*)(smem + SM_A0L + o1) = l1;
        }
    }
    __syncthreads();

    float acc[4][4][4];
    #pragma unroll
    for (int m = 0; m < 4; m++)
        #pragma unroll
        for (int nt = 0; nt < 4; nt++)
            #pragma unroll
            for (int r = 0; r < 4; r++) acc[m][nt][r] = 0.f;
    #pragma unroll 1
    for (int k16 = 0; k16 < 4; k16++) {
        uint2 bh[4], bl[4];
        #pragma unroll
        for (int nt = 0; nt < 4; nt++) {
            int f = ((k16 * 32 + wid * 4 + nt) * 2) * 32 + lane;
            bh[nt] = g_W0f[f];
            bl[nt] = g_W0f[f + 32];
        }
        #pragma unroll
        for (int m = 0; m < 4; m++) {
            uint32_t ah[4], al[4];
            uint32_t aa = SWZ((uint32_t)((m * 16 + aro) * 128 + (k16 * 16 + aco) * 2));
            ldsm4(ah, smb + SM_A0H + aa);
            ldsm4(al, smb + SM_A0L + aa);
            #pragma unroll
            for (int nt = 0; nt < 4; nt++) {
                mma16816(acc[m][nt], ah, (const uint32_t*)&bh[nt]);
                mma16816(acc[m][nt], ah, (const uint32_t*)&bl[nt]);
                mma16816(acc[m][nt], al, (const uint32_t*)&bh[nt]);
            }
        }
    }
    __syncthreads();

    #pragma unroll
    for (int m = 0; m < 4; m++)
        #pragma unroll
        for (int nt = 0; nt < 4; nt++) {
            int c0 = wid * 32 + 8 * nt + 2 * tq;
            float v0 = acc[m][nt][0] + b0s[c0];
            float v1 = acc[m][nt][1] + b0s[c0 + 1];
            float v2 = acc[m][nt][2] + b0s[c0];
            float v3 = acc[m][nt][3] + b0s[c0 + 1];
            v0 = v0 > 0.f ? v0 : 0.01f * v0;
            v1 = v1 > 0.f ? v1 : 0.01f * v1;
            v2 = v2 > 0.f ? v2 : 0.01f * v2;
            v3 = v3 > 0.f ? v3 : 0.01f * v3;
            int r0 = 16 * m + g, r1 = r0 + 8;
            __nv_bfloat162 h01 = split_hi(v0, v1), l01 = split_lo(v0, v1, h01);
            __nv_bfloat162 h23 = split_hi(v2, v3), l23 = split_lo(v2, v3, h23);
            *(__nv_bfloat162*)(smem + SM_A1H + r0 * PA1 + c0 * 2) = h01;
            *(__nv_bfloat162*)(smem + SM_A1L + r0 * PA1 + c0 * 2) = l01;
            *(__nv_bfloat162*)(smem + SM_A1H + r1 * PA1 + c0 * 2) = h23;
            *(__nv_bfloat162*)(smem + SM_A1L + r1 * PA1 + c0 * 2) = l23;
        }
    __syncthreads();

    float a2[4][4][4];
    #pragma unroll
    for (int m = 0; m < 4; m++)
        #pragma unroll
        for (int nt = 0; nt < 4; nt++)
            #pragma unroll
            for (int r = 0; r < 4; r++) a2[m][nt][r] = 0.f;
    #pragma unroll 1
    for (int c = 0; c < 8; c++) {
        #pragma unroll
        for (int k16 = 0; k16 < 2; k16++) {
            uint2 bh[4], bl[4];
            #pragma unroll
            for (int nt = 0; nt < 4; nt++) {
                int f = (((c * 2 + k16) * 32 + wid * 4 + nt) * 2) * 32 + lane;
                bh[nt] = g_W1f[f];
                bl[nt] = g_W1f[f + 32];
            }
            #pragma unroll
            for (int m = 0; m < 4; m++) {
                uint32_t ah[4], al[4];
                uint32_t aa = (uint32_t)((m * 16 + aro) * PA1 + (c * 32 + k16 * 16 + aco) * 2);
                ldsm4(ah, smb + SM_A1H + aa);
                ldsm4(al, smb + SM_A1L + aa);
                #pragma unroll
                for (int nt = 0; nt < 4; nt++) {
                    mma16816(a2[m][nt], ah, (const uint32_t*)&bh[nt]);
                    mma16816(a2[m][nt], ah, (const uint32_t*)&bl[nt]);
                    mma16816(a2[m][nt], al, (const uint32_t*)&bh[nt]);
                }
            }
        }
    }

    float* red = (float*)(smem + SM_RED);
    float p[4][2];
    #pragma unroll
    for (int m = 0; m < 4; m++) { p[m][0] = 0.f; p[m][1] = 0.f; }
    #pragma unroll
    for (int m = 0; m < 4; m++)
        #pragma unroll
        for (int nt = 0; nt < 4; nt++) {
            int c0 = wid * 32 + 8 * nt + 2 * tq;
            float w0v = ows[c0], w1v = ows[c0 + 1];
            float bb0 = b1s[c0], bb1 = b1s[c0 + 1];
            float v0 = a2[m][nt][0] + bb0;
            float v1 = a2[m][nt][1] + bb1;
            float v2 = a2[m][nt][2] + bb0;
            float v3 = a2[m][nt][3] + bb1;
            v0 = v0 > 0.f ? v0 : 0.01f * v0;
            v1 = v1 > 0.f ? v1 : 0.01f * v1;
            v2 = v2 > 0.f ? v2 : 0.01f * v2;
            v3 = v3 > 0.f ? v3 : 0.01f * v3;
            p[m][0] = fmaf(v0, w0v, p[m][0]);
            p[m][0] = fmaf(v1, w1v, p[m][0]);
            p[m][1] = fmaf(v2, w0v, p[m][1]);
            p[m][1] = fmaf(v3, w1v, p[m][1]);
        }
    #pragma unroll
    for (int off = 1; off <= 2; off <<= 1)
        #pragma unroll
        for (int m = 0; m < 4; m++) {
            p[m][0] += __shfl_xor_sync(0xffffffffu, p[m][0], off);
            p[m][1] += __shfl_xor_sync(0xffffffffu, p[m][1], off);
        }
    if (tq == 0) {
        #pragma unroll
        for (int m = 0; m < 4; m++) {
            red[wid * 64 + 16 * m + g]     = p[m][0];
            red[wid * 64 + 16 * m + g + 8] = p[m][1];
        }
    }
    __syncthreads();
    if (tid < 64) {
        float s = __ldg(ob);
        #pragma unroll
        for (int w8 = 0; w8 < 8; w8++) s += red[w8 * 64 + tid];
        val[row0 + tid] = s;
    }
}

extern "C" void kernel_launch(void* const* d_in, const int* in_sizes, int n_in,
                              void* d_out, int out_size) {
    const float* obs   = (const float*)d_in[0];
    const float* rnn   = (const float*)d_in[1];
    const float* eAW   = (const float*)d_in[2];
    const float* eAb   = (const float*)d_in[3];
    const float* eMW   = (const float*)d_in[4];
    const float* eMb   = (const float*)d_in[5];
    const float* aWih  = (const float*)d_in[6];
    const float* aWhh  = (const float*)d_in[7];
    const float* abih  = (const float*)d_in[8];
    const float* abhh  = (const float*)d_in[9];
    const float* mWih  = (const float*)d_in[10];
    const float* mWhh  = (const float*)d_in[11];
    const float* mbih  = (const float*)d_in[12];
    const float* mbhh  = (const float*)d_in[13];
    const float* Win   = (const float*)d_in[14];
    const float* bin   = (const float*)d_in[15];
    const float* Wout  = (const float*)d_in[16];
    const float* bout  = (const float*)d_in[17];
    const float* W0    = (const float*)d_in[18];
    const float* b0    = (const float*)d_in[19];
    const float* W1    = (const float*)d_in[20];
    const float* b1    = (const float*)d_in[21];
    const float* oW    = (const float*)d_in[22];
    const float* ob    = (const float*)d_in[23];

    float* out_val = (float*)d_out;
    float* out_h   = (float*)d_out + Nq;

    k_packw<<<178, 256>>>(W0, W1, aWih, aWhh, abih, abhh, eAW, eAb,
                          mWih, mWhh, mbih, mbhh, eMW, eMb, Win, Wout);
    k_packg_x<<<6144, 256>>>(obs);
    k_gru_tc<<<384, 32>>>(rnn, out_h);
    k_attn_tc<<<Nq / 16 / 8, 256>>>(obs, bin, bout);
    cudaFuncSetAttribute(k_mlp_h, cudaFuncAttributeMaxDynamicSharedMemorySize, SM_TOT);
    k_mlp_h<<<Nq / 64, 256, SM_TOT>>>(b0, b1, oW, ob, out_val);
}

// round 17
// speedup vs baseline: 1.2863x; 1.0530x over previous
#include <cuda_runtime.h>
#include <cuda_bf16.h>
#include <cstdint>

#define Bq 2048
#define Tq 128
#define Nq (Bq*Tq)

// ---------------- scratch (no allocations allowed) ----------------
__device__ float g_air[(size_t)Nq * 32];
__device__ float g_m1 [(size_t)Nq * 32];
__device__ float g_m2 [(size_t)Nq * 32];
// MLP weights prepacked in mma B-fragment layout (hi/lo split-bf16)
__device__ uint2 g_W0f[8192];
__device__ uint2 g_W1f[32768];
// attention weights as B-fragments: [mat(4)][kt(2)][nt(4)][part(2)][lane(32)]
__device__ uint2 g_Waf[2048];
// GRU tensor-core prepack
__device__ uint2  g_gB[2 * 36 * 2 * 32];
__device__ float  g_gBias[2 * 128];
// X fragments compressed (r2/r3 structurally zero)
__device__ uint4  g_gX[(size_t)384 * 128 * 32];

__device__ __forceinline__ float tanhap(float x) {
    float y;
    asm("tanh.approx.f32 %0, %1;" : "=f"(y) : "f"(x));
    return y;
}
__device__ __forceinline__ float fsig(float x) {
    return fmaf(0.5f, tanhap(0.5f * x), 0.5f);
}

__device__ __forceinline__ uint32_t smem_u32(const void* p) {
    uint32_t a;
    asm("{ .reg .u64 t; cvta.to.shared.u64 t, %1; cvt.u32.u64 %0, t; }" : "=r"(a) : "l"(p));
    return a;
}
__device__ __forceinline__ void ldsm4(uint32_t* a, uint32_t addr) {
    asm volatile("ldmatrix.sync.aligned.m8n8.x4.shared.b16 {%0,%1,%2,%3}, [%4];"
        : "=r"(a[0]), "=r"(a[1]), "=r"(a[2]), "=r"(a[3]) : "r"(addr));
}
__device__ __forceinline__ void mma16816(float* c, const uint32_t* a, const uint32_t* b) {
    asm volatile("mma.sync.aligned.m16n8k16.row.col.f32.bf16.bf16.f32 "
        "{%0,%1,%2,%3}, {%4,%5,%6,%7}, {%8,%9}, {%0,%1,%2,%3};"
        : "+f"(c[0]), "+f"(c[1]), "+f"(c[2]), "+f"(c[3])
        : "r"(a[0]), "r"(a[1]), "r"(a[2]), "r"(a[3]), "r"(b[0]), "r"(b[1]));
}
#define SWZ(x) ((x) ^ (((x) >> 3) & 0x70))

__device__ __forceinline__ __nv_bfloat162 split_hi(float a, float b) {
    __nv_bfloat162 h; h.x = __float2bfloat16(a); h.y = __float2bfloat16(b); return h;
}
__device__ __forceinline__ __nv_bfloat162 split_lo(float a, float b, __nv_bfloat162 h) {
    __nv_bfloat162 l;
    l.x = __float2bfloat16(a - __bfloat162float(h.x));
    l.y = __float2bfloat16(b - __bfloat162float(h.y));
    return l;
}
__device__ __forceinline__ uint32_t bf2u(__nv_bfloat162 v) {
    return *reinterpret_cast<uint32_t*>(&v);
}
__device__ __forceinline__ void split2(float a, float b, uint32_t& hi, uint32_t& lo) {
    __nv_bfloat162 h = split_hi(a, b);
    __nv_bfloat162 l = split_lo(a, b, h);
    hi = bf2u(h); lo = bf2u(l);
}

// GRU tile-pair tables (kt-outer)
#define GRU_PNT {0,1,2,3,4,5,6,7,8,9,10,11, 0,1,2,3,4,5,6,7,8,9,10,11, 0,1,2,3,4,5,6,7,12,13,14,15}
#define GRU_PKT {0,0,0,0,0,0,0,0,0,0,0,0,  1,1,1,1,1,1,1,1,1,1,1,1,   2,2,2,2,2,2,2,2,2,2,2,2}

__device__ __forceinline__ float gru_bval(
    int k, int n, const float* Whh, const float* Wih, const float* encW, int KIN)
{
    int blk = n >> 5, j = n & 31;
    if (k < 32) {
        if (blk == 3) return 0.f;
        return Whh[(blk * 32 + j) * 32 + k];
    }
    int f = k - 32;
    if (f >= KIN || blk == 2) return 0.f;
    int row = (blk == 3) ? 64 + j : blk * 32 + j;
    float s = 0.f;
    #pragma unroll
    for (int m = 0; m < 32; m++) s = fmaf(Wih[row * 32 + m], encW[m * KIN + f], s);
    return s;
}

// ====== merged weight prepack (R16 verbatim) =====
__global__ void k_packw(
    const float* __restrict__ W0, const float* __restrict__ W1,
    const float* __restrict__ aWih, const float* __restrict__ aWhh,
    const float* __restrict__ abih, const float* __restrict__ abhh,
    const float* __restrict__ eAW,  const float* __restrict__ eAb,
    const float* __restrict__ mWih, const float* __restrict__ mWhh,
    const float* __restrict__ mbih, const float* __restrict__ mbhh,
    const float* __restrict__ eMW,  const float* __restrict__ eMb,
    const float* __restrict__ Win,  const float* __restrict__ Wout)
{
    int tid = blockIdx.x * 256 + threadIdx.x;
    int lane = tid & 31, tq = lane & 3, g = lane >> 2;
    if (tid < 8192) {
        int q = tid >> 5;
        int part = q & 1; q >>= 1;
        int ntg = q & 31;
        int k16 = q >> 5;
        int n = ntg * 8 + g;
        uint32_t rr[2];
        #pragma unroll
        for (int r = 0; r < 2; r++) {
            int k0 = k16 * 16 + tq * 2 + r * 8;
            float v0 = W0[n * 64 + k0], v1 = W0[n * 64 + k0 + 1];
            __nv_bfloat162 hh = split_hi(v0, v1);
            if (part == 0) rr[r] = bf2u(hh);
            else           rr[r] = bf2u(split_lo(v0, v1, hh));
        }
        g_W0f[tid] = make_uint2(rr[0], rr[1]);
    } else if (tid < 40960) {
        int j = tid - 8192;
        int q = j >> 5;
        int part = q & 1; q >>= 1;
        int ntg = q & 31;
        int ck = q >> 5;
        int n = ntg * 8 + g;
        uint32_t rr[2];
        #pragma unroll
        for (int r = 0; r < 2; r++) {
            int k0 = ck * 16 + tq * 2 + r * 8;
            float v0 = W1[n * 256 + k0], v1 = W1[n * 256 + k0 + 1];
            __nv_bfloat162 hh = split_hi(v0, v1);
            if (part == 0) rr[r] = bf2u(hh);
            else           rr[r] = bf2u(split_lo(v0, v1, hh));
        }
        g_W1f[j] = make_uint2(rr[0], rr[1]);
    } else if (tid < 40960 + 2304) {
        const int PNT[36] = GRU_PNT;
        const int PKT[36] = GRU_PKT;
        int u = tid - 40960;
        int p = (u >> 5) % 36;
        int ty = u / (36 * 32);
        const float* Whh = ty ? mWhh : aWhh;
        const float* Wih = ty ? mWih : aWih;
        const float* eW  = ty ? eMW  : eAW;
        int KIN = ty ? 4 : 7;
        int n = PNT[p] * 8 + g;
        uint32_t rh[2], rl[2];
        #pragma unroll
        for (int r = 0; r < 2; r++) {
            int k0 = PKT[p] * 16 + tq * 2 + r * 8;
            float v0 = gru_bval(k0,     n, Whh, Wih, eW, KIN);
            float v1 = gru_bval(k0 + 1, n, Whh, Wih, eW, KIN);
            __nv_bfloat162 hh = split_hi(v0, v1);
            __nv_bfloat162 ll = split_lo(v0, v1, hh);
            rh[r] = bf2u(hh); rl[r] = bf2u(ll);
        }
        int base = (ty * 72 + p * 2) * 32 + lane;
        g_gB[base]      = make_uint2(rh[0], rh[1]);
        g_gB[base + 32] = make_uint2(rl[0], rl[1]);
    } else if (tid < 40960 + 2304 + 256) {
        int u = tid - 40960 - 2304;
        int ty = u >> 7, n = u & 127;
        const float* Wih = ty ? mWih : aWih;
        const float* bih = ty ? mbih : abih;
        const float* bhh = ty ? mbhh : abhh;
        const float* eB  = ty ? eMb  : eAb;
        int blk = n >> 5, j = n & 31;
        float b;
        if (blk == 2) {
            b = bhh[64 + j];
        } else {
            int row = (blk == 3) ? 64 + j : blk * 32 + j;
            float bc = bih[row];
            #pragma unroll
            for (int m = 0; m < 32; m++) bc = fmaf(Wih[row * 32 + m], eB[m], bc);
            b = (blk < 2) ? bc + bhh[row] : bc;
        }
        g_gBias[ty * 128 + n] = b;
    } else if (tid < 40960 + 2304 + 256 + 2048) {
        int u = tid - 40960 - 2304 - 256;
        int q = u >> 5;
        int part = q & 1; q >>= 1;
        int nt = q & 3; q >>= 2;
        int kt = q & 1;
        int m = q >> 1;
        int n = nt * 8 + g;
        const float* M = (m < 3) ? (Win + (m * 32 + n) * 32) : (Wout + n * 32);
        uint32_t rr[2];
        #pragma unroll
        for (int r = 0; r < 2; r++) {
            int k0 = kt * 16 + tq * 2 + r * 8;
            float v0 = M[k0], v1 = M[k0 + 1];
            __nv_bfloat162 hh = split_hi(v0, v1);
            if (part == 0) rr[r] = bf2u(hh);
            else           rr[r] = bf2u(split_lo(v0, v1, hh));
        }
        g_Waf[((m * 2 + kt) * 4 + nt) * 64 + part * 32 + lane] = make_uint2(rr[0], rr[1]);
    }
}

// X A-fragment prepack (R16 verbatim)
__global__ void k_packg_x(const float* __restrict__ obs) {
    int tid = blockIdx.x * 256 + threadIdx.x;
    int lane = tid & 31;
    int s = tid >> 5;
    int t = s & 127;
    int gr = s >> 7;
    int g = lane >> 2, tq = lane & 3;

    int KIN, xoff;
    int b0;
    if (gr < 128) { KIN = 7; xoff = 8; b0 = gr * 16; }
    else {
        int gi = gr - 128;
        KIN = 4;
        xoff = (gi < 128) ? 0 : 4;
        b0 = (gi < 128) ? gi * 16 : (gi - 128) * 16;
    }
    uint32_t hr[2], lr[2];
    #pragma unroll
    for (int r = 0; r < 2; r++) {
        int row = g + 8 * r;
        int k0 = tq * 2;
        float v0 = 0.f, v1 = 0.f;
        if (k0 < KIN)
            v0 = obs[(size_t)(b0 + row) * Tq * 15 + t * 15 + xoff + k0];
        if (k0 + 1 < KIN)
            v1 = obs[(size_t)(b0 + row) * Tq * 15 + t * 15 + xoff + k0 + 1];
        split2(v0, v1, hr[r], lr[r]);
    }
    g_gX[(size_t)(gr * 128 + t) * 32 + lane] = make_uint4(hr[0], hr[1], lr[0], lr[1]);
}

// ====== GRU: tensor-core recurrence (R16 verbatim) ======
__global__ void __launch_bounds__(32) k_gru_tc(
    const float* __restrict__ rnn, float* __restrict__ next_h)
{
    const int PNT[36] = GRU_PNT;
    const int PKT[36] = GRU_PKT;
    int lane = threadIdx.x & 31;
    int w = blockIdx.x;
    int g = lane >> 2, tq = lane & 3;

    int ty; float* featb; int ib; bool is_air = (w < 128);
    if (is_air) { ty = 0; featb = g_air; ib = w * 16; }
    else {
        ty = 1;
        int gi = w - 128;
        if (gi < 128) { featb = g_m1; ib = gi * 16; }
        else          { featb = g_m2; ib = (gi - 128) * 16; }
    }
    int gi = w - 128;

    float hv[4][4];
    #pragma unroll
    for (int nt = 0; nt < 4; nt++) {
        int col = nt * 8 + 2 * tq;
        #pragma unroll
        for (int rh = 0; rh < 2; rh++) {
            int row = g + 8 * rh;
            const float* src;
            if (is_air) src = rnn + (size_t)(w * 16 + row) * 96 + col;
            else {
                int i = gi * 16 + row;
                src = rnn + (size_t)(i >> 1) * 96 + 32 + 32 * (i & 1) + col;
            }
            float2 v = *(const float2*)src;
            hv[nt][rh * 2]     = v.x;
            hv[nt][rh * 2 + 1] = v.y;
        }
    }
    float bias[16][2];
    #pragma unroll
    for (int nt = 0; nt < 16; nt++) {
        float2 v = *(const float2*)(g_gBias + ty * 128 + nt * 8 + 2 * tq);
        bias[nt][0] = v.x; bias[nt][1] = v.y;
    }
    uint32_t Ah[2][4], Al[2][4];
    #pragma unroll
    for (int nt = 0; nt < 4; nt++) {
        int kt = nt >> 1;
        int o = (nt & 1) ? 2 : 0;
        split2(hv[nt][0], hv[nt][1], Ah[kt][o],     Al[kt][o]);
        split2(hv[nt][2], hv[nt][3], Ah[kt][o + 1], Al[kt][o + 1]);
    }

    const uint2* gBb = g_gB + ty * 72 * 32 + lane;
    const uint4* gXb = g_gX + (size_t)w * 128 * 32 + lane;
    float* fr0 = featb + (size_t)(ib + g)     * Tq * 32 + 2 * tq;
    float* fr1 = featb + (size_t)(ib + g + 8) * Tq * 32 + 2 * tq;

    uint4 x_cur = gXb[0];

    #pragma unroll 1
    for (int t = 0; t < Tq; t++) {
        int tn = (t + 1 < Tq) ? t + 1 : t;
        uint4 x_nxt = gXb[(size_t)tn * 32];

        uint32_t Xh[4] = {x_cur.x, x_cur.y, 0u, 0u};
        uint32_t Xl[4] = {x_cur.z, x_cur.w, 0u, 0u};
        float C[16][4];
        #pragma unroll
        for (int nt = 0; nt < 16; nt++) {
            C[nt][0] = bias[nt][0]; C[nt][1] = bias[nt][1];
            C[nt][2] = bias[nt][0]; C[nt][3] = bias[nt][1];
        }
        #pragma unroll
        for (int p = 0; p < 36; p++) {
            int nt = PNT[p], kt = PKT[p];
            uint2 bh = gBb[(p * 2) * 32];
            uint2 bl = gBb[(p * 2 + 1) * 32];
            const uint32_t* ah = (kt == 2) ? Xh : Ah[kt];
            const uint32_t* al = (kt == 2) ? Xl : Al[kt];
            mma16816(C[nt], ah, (const uint32_t*)&bh);
            mma16816(C[nt], ah, (const uint32_t*)&bl);
            mma16816(C[nt], al, (const uint32_t*)&bh);
        }
        #pragma unroll
        for (int nt = 0; nt < 4; nt++) {
            #pragma unroll
            for (int j = 0; j < 4; j++) {
                float r = fsig(C[nt][j]);
                float z = fsig(C[nt + 4][j]);
                float n = tanhap(fmaf(r, C[nt + 8][j], C[nt + 12][j]));
                hv[nt][j] = n + z * (hv[nt][j] - n);
            }
            *(float2*)(fr0 + (size_t)t * 32 + nt * 8) = make_float2(hv[nt][0], hv[nt][1]);
            *(float2*)(fr1 + (size_t)t * 32 + nt * 8) = make_float2(hv[nt][2], hv[nt][3]);
            int kt = nt >> 1;
            int o = (nt & 1) ? 2 : 0;
            split2(hv[nt][0], hv[nt][1], Ah[kt][o],     Al[kt][o]);
            split2(hv[nt][2], hv[nt][3], Ah[kt][o + 1], Al[kt][o + 1]);
        }
        x_cur = x_nxt;
    }
    #pragma unroll
    for (int nt = 0; nt < 4; nt++) {
        int col = nt * 8 + 2 * tq;
        #pragma unroll
        for (int rh = 0; rh < 2; rh++) {
            int row = g + 8 * rh;
            float2 v = make_float2(hv[nt][rh * 2], hv[nt][rh * 2 + 1]);
            float* dst;
            if (is_air) dst = next_h + (size_t)(w * 16 + row) * 96 + col;
            else {
                int i = gi * 16 + row;
                dst = next_h + (size_t)(i >> 1) * 96 + 32 + 32 * (i & 1) + col;
            }
            *(float2*)dst = v;
        }
    }
}

// ====== attention helpers (R15) ======
__device__ __forceinline__ void load_frag(const float* base, int ra, int rb, int tq,
                                          uint32_t Ah[2][4], uint32_t Al[2][4]) {
    #pragma unroll
    for (int kt = 0; kt < 2; kt++) {
        float2 a0 = *(const float2*)(base + (size_t)ra * 32 + kt * 16 + 2 * tq);
        float2 b0 = *(const float2*)(base + (size_t)rb * 32 + kt * 16 + 2 * tq);
        float2 a2 = *(const float2*)(base + (size_t)ra * 32 + kt * 16 + 2 * tq + 8);
        float2 b2 = *(const float2*)(base + (size_t)rb * 32 + kt * 16 + 2 * tq + 8);
        split2(a0.x, a0.y, Ah[kt][0], Al[kt][0]);
        split2(b0.x, b0.y, Ah[kt][1], Al[kt][1]);
        split2(a2.x, a2.y, Ah[kt][2], Al[kt][2]);
        split2(b2.x, b2.y, Ah[kt][3], Al[kt][3]);
    }
}
__device__ __forceinline__ void attn_gemm(float C[4][4], const uint32_t Ah[2][4],
                                          const uint32_t Al[2][4], int mat, int lane) {
    #pragma unroll
    for (int nt = 0; nt < 4; nt++) {
        C[nt][0] = 0.f; C[nt][1] = 0.f; C[nt][2] = 0.f; C[nt][3] = 0.f;
    }
    #pragma unroll
    for (int kt = 0; kt < 2; kt++)
        #pragma unroll
        for (int nt = 0; nt < 4; nt++) {
            int base = ((mat * 2 + kt) * 4 + nt) * 64 + lane;
            uint2 bh = g_Waf[base];
            uint2 bl = g_Waf[base + 32];
            mma16816(C[nt], Ah[kt], (const uint32_t*)&bh);
            mma16816(C[nt], Ah[kt], (const uint32_t*)&bl);
            mma16816(C[nt], Al[kt], (const uint32_t*)&bh);
        }
}

// ======= fused attention + HMMA MLP =======
#define SM_B0  0
#define SM_B1  1024
#define SM_OW  2048
#define SM_A1H 3072
#define SM_A1L 36864
#define SM_RED 70656
#define SM_TOT 72704
#define SM_A0H 3072
#define SM_A0L 11264
#define PA1 528

__global__ void __launch_bounds__(256, 2) k_mlp_f(
    const float* __restrict__ obs,
    const float* __restrict__ bin, const float* __restrict__ bout,
    const float* __restrict__ b0, const float* __restrict__ b1,
    const float* __restrict__ oW, const float* __restrict__ ob,
    float* __restrict__ val)
{
    extern __shared__ char smem[];
    uint32_t smb = smem_u32(smem);
    int tid = threadIdx.x, wid = tid >> 5, lane = tid & 31;
    int g = lane >> 2, tq = lane & 3;
    int row0 = blockIdx.x * 64;

    float* b0s = (float*)(smem + SM_B0);
    float* b1s = (float*)(smem + SM_B1);
    float* ows = (float*)(smem + SM_OW);
    b0s[tid] = b0[tid]; b1s[tid] = b1[tid]; ows[tid] = oW[tid];

    int aro = lane & 15;
    int aco = (lane >> 1) & 8;

    // ---- phase 0: warps 0-3 attention (16 rows each) -> A0 attn half;
    //               warps 4-7 split air -> A0 air half ----
    if (wid < 4) {
        int rl = wid * 16 + g;              // local row of out[...][0..1]
        int ra = row0 + rl, rb = ra + 8;

        const float T1 = 1.001e-5f, T0 = 1e-8f;
        bool mk0a, mk1a, mk0b, mk1b;
        {
            const float* oa = obs + (size_t)ra * 15;
            const float* oq = obs + (size_t)rb * 15;
            mk0a = (fabsf(oa[0]-1.f)<=T1)&&(fabsf(oa[1])<=T0)&&(fabsf(oa[2]-1.f)<=T1)&&(fabsf(oa[3])<=T0);
            mk1a = (fabsf(oa[4]-1.f)<=T1)&&(fabsf(oa[5])<=T0)&&(fabsf(oa[6]-1.f)<=T1)&&(fabsf(oa[7])<=T0);
            mk0b = (fabsf(oq[0]-1.f)<=T1)&&(fabsf(oq[1])<=T0)&&(fabsf(oq[2]-1.f)<=T1)&&(fabsf(oq[3])<=T0);
            mk1b = (fabsf(oq[4]-1.f)<=T1)&&(fabsf(oq[5])<=T0)&&(fabsf(oq[6]-1.f)<=T1)&&(fabsf(oq[7])<=T0);
        }
        float2 bq[4], bk[4], bv[4], bo2[4];
        #pragma unroll
        for (int nt = 0; nt < 4; nt++) {
            int col = nt * 8 + 2 * tq;
            bq[nt]  = *(const float2*)(bin + col);
            bk[nt]  = *(const float2*)(bin + 32 + col);
            bv[nt]  = *(const float2*)(bin + 64 + col);
            bo2[nt] = *(const float2*)(bout + col);
        }

        float q[4][4];
        {
            uint32_t Ah[2][4], Al[2][4];
            load_frag(g_air, ra, rb, tq, Ah, Al);
            attn_gemm(q, Ah, Al, 0, lane);
        }
        #pragma unroll
        for (int nt = 0; nt < 4; nt++) {
            q[nt][0] += bq[nt].x; q[nt][1] += bq[nt].y;
            q[nt][2] += bq[nt].x; q[nt][3] += bq[nt].y;
        }

        float k1[4][4], v1[4][4], k2[4][4], v2[4][4];
        {
            uint32_t Ah[2][4], Al[2][4];
            load_frag(g_m1, ra, rb, tq, Ah, Al);
            attn_gemm(k1, Ah, Al, 1, lane);
            attn_gemm(v1, Ah, Al, 2, lane);
            load_frag(g_m2, ra, rb, tq, Ah, Al);
            attn_gemm(k2, Ah, Al, 1, lane);
            attn_gemm(v2, Ah, Al, 2, lane);
        }
        #pragma unroll
        for (int nt = 0; nt < 4; nt++) {
            k1[nt][0] += bk[nt].x; k1[nt][1] += bk[nt].y; k1[nt][2] += bk[nt].x; k1[nt][3] += bk[nt].y;
            k2[nt][0] += bk[nt].x; k2[nt][1] += bk[nt].y; k2[nt][2] += bk[nt].x; k2[nt][3] += bk[nt].y;
            v1[nt][0] += bv[nt].x; v1[nt][1] += bv[nt].y; v1[nt][2] += bv[nt].x; v1[nt][3] += bv[nt].y;
            v2[nt][0] += bv[nt].x; v2[nt][1] += bv[nt].y; v2[nt][2] += bv[nt].x; v2[nt][3] += bv[nt].y;
        }

        float s1[2][2], s2[2][2];
        #pragma unroll
        for (int h = 0; h < 2; h++)
            #pragma unroll
            for (int rj = 0; rj < 2; rj++) {
                int jb = rj * 2;
                float t1 = 0.f, t2 = 0.f;
                #pragma unroll
                for (int u = 0; u < 2; u++) {
                    int nt = 2 * h + u;
                    t1 += q[nt][jb] * k1[nt][jb] + q[nt][jb+1] * k1[nt][jb+1];
                    t2 += q[nt][jb] * k2[nt][jb] + q[nt][jb+1] * k2[nt][jb+1];
                }
                s1[h][rj] = t1; s2[h][rj] = t2;
            }
        #pragma unroll
        for (int off = 1; off <= 2; off <<= 1)
            #pragma unroll
            for (int h = 0; h < 2; h++)
                #pragma unroll
                for (int rj = 0; rj < 2; rj++) {
                    s1[h][rj] += __shfl_xor_sync(0xffffffffu, s1[h][rj], off);
                    s2[h][rj] += __shfl_xor_sync(0xffffffffu, s2[h][rj], off);
                }

        float w1[2][2], w2[2][2];
        #pragma unroll
        for (int rj = 0; rj < 2; rj++) {
            bool mk0 = rj ? mk0b : mk0a;
            bool mk1 = rj ? mk1b : mk1a;
            #pragma unroll
            for (int h = 0; h < 2; h++) {
                float a = s1[h][rj] * 0.25f + (mk0 ? -1e9f : 0.f);
                float b = s2[h][rj] * 0.25f + (mk1 ? -1e9f : 0.f);
                float m = fmaxf(a, b);
                float e1 = __expf(a - m), e2 = __expf(b - m);
                float inv = __fdividef(1.0f, e1 + e2);
                w1[h][rj] = e1 * inv; w2[h][rj] = e2 * inv;
            }
        }

        uint32_t Ch[2][4], Cl[2][4];
        #pragma unroll
        for (int nt = 0; nt < 4; nt++) {
            int h = nt >> 1;
            float c0 = w1[h][0] * v1[nt][0] + w2[h][0] * v2[nt][0];
            float c1 = w1[h][0] * v1[nt][1] + w2[h][0] * v2[nt][1];
            float c2 = w1[h][1] * v1[nt][2] + w2[h][1] * v2[nt][2];
            float c3 = w1[h][1] * v1[nt][3] + w2[h][1] * v2[nt][3];
            int kt = nt >> 1;
            int o = (nt & 1) ? 2 : 0;
            split2(c0, c1, Ch[kt][o],     Cl[kt][o]);
            split2(c2, c3, Ch[kt][o + 1], Cl[kt][o + 1]);
        }

        float out[4][4];
        attn_gemm(out, Ch, Cl, 3, lane);
        bool za = mk0a && mk1a, zb = mk0b && mk1b;
        #pragma unroll
        for (int nt = 0; nt < 4; nt++) {
            float o0 = za ? 0.f : (out[nt][0] + bo2[nt].x);
            float o1 = za ? 0.f : (out[nt][1] + bo2[nt].y);
            float o2 = zb ? 0.f : (out[nt][2] + bo2[nt].x);
            float o3 = zb ? 0.f : (out[nt][3] + bo2[nt].y);
            int cc2 = (nt * 8 + 2 * tq) * 2;            // byte offset of col pair within attn half
            uint32_t hi, lo;
            split2(o0, o1, hi, lo);
            *(uint32_t*)(smem + SM_A0H + SWZ((uint32_t)(rl * 128 + 64 + cc2))) = hi;
            *(uint32_t*)(smem + SM_A0L + SWZ((uint32_t)(rl * 128 + 64 + cc2))) = lo;
            split2(o2, o3, hi, lo);
            *(uint32_t*)(smem + SM_A0H + SWZ((uint32_t)((rl + 8) * 128 + 64 + cc2))) = hi;
            *(uint32_t*)(smem + SM_A0L + SWZ((uint32_t)((rl + 8) * 128 + 64 + cc2))) = lo;
        }
    } else {
        int t4 = tid - 128;                 // 0..127
        #pragma unroll
        for (int qq = 0; qq < 4; qq++) {
            int id = t4 + 128 * qq;         // 0..511 = 64 rows x 8 float4
            int r = id >> 3, c4 = id & 7;
            float4 v = ((const float4*)(g_air + (size_t)(row0 + r) * 32))[c4];
            __nv_bfloat162 h0 = split_hi(v.x, v.y), l0 = split_lo(v.x, v.y, h0);
            __nv_bfloat162 h1 = split_hi(v.z, v.w), l1 = split_lo(v.z, v.w, h1);
            uint32_t o0 = SWZ((uint32_t)(r * 128 + c4 * 8));
            uint32_t o1 = SWZ((uint32_t)(r * 128 + c4 * 8 + 4));
            *(__nv_bfloat162*)(smem + SM_A0H + o0) = h0;
            *(__nv_bfloat162*)(smem + SM_A0H + o1) = h1;
            *(__nv_bfloat162*)(smem + SM_A0L + o0) = l0;
            *(__nv_bfloat162*)(smem + SM_A0L + o1) = l1;
        }
    }
    __syncthreads();

    // ---- layer 0 ----
    float acc[4][4][4];
    #pragma unroll
    for (int m = 0; m < 4; m++)
        #pragma unroll
        for (int nt = 0; nt < 4; nt++)
            #pragma unroll
            for (int r = 0; r < 4; r++) acc[m][nt][r] = 0.f;
    #pragma unroll 1
    for (int k16 = 0; k16 < 4; k16++) {
        uint2 bh[4], bl[4];
        #pragma unroll
        for (int nt = 0; nt < 4; nt++) {
            int f = ((k16 * 32 + wid * 4 + nt) * 2) * 32 + lane;
            bh[nt] = g_W0f[f];
            bl[nt] = g_W0f[f + 32];
        }
        #pragma unroll
        for (int m = 0; m < 4; m++) {
            uint32_t ah[4], al[4];
            uint32_t aa = SWZ((uint32_t)((m * 16 + aro) * 128 + (k16 * 16 + aco) * 2));
            ldsm4(ah, smb + SM_A0H + aa);
            ldsm4(al, smb + SM_A0L + aa);
            #pragma unroll
            for (int nt = 0; nt < 4; nt++) {
                mma16816(acc[m][nt], ah, (const uint32_t*)&bh[nt]);
                mma16816(acc[m][nt], ah, (const uint32_t*)&bl[nt]);
                mma16816(acc[m][nt], al, (const uint32_t*)&bh[nt]);
            }
        }
    }
    __syncthreads();

    // ---- bias+leaky -> split -> A1 ----
    #pragma unroll
    for (int m = 0; m < 4; m++)
        #pragma unroll
        for (int nt = 0; nt < 4; nt++) {
            int c0 = wid * 32 + 8 * nt + 2 * tq;
            float v0 = acc[m][nt][0] + b0s[c0];
            float v1 = acc[m][nt][1] + b0s[c0 + 1];
            float v2 = acc[m][nt][2] + b0s[c0];
            float v3 = acc[m][nt][3] + b0s[c0 + 1];
            v0 = v0 > 0.f ? v0 : 0.01f * v0;
            v1 = v1 > 0.f ? v1 : 0.01f * v1;
            v2 = v2 > 0.f ? v2 : 0.01f * v2;
            v3 = v3 > 0.f ? v3 : 0.01f * v3;
            int r0 = 16 * m + g, r1 = r0 + 8;
            __nv_bfloat162 h01 = split_hi(v0, v1), l01 = split_lo(v0, v1, h01);
            __nv_bfloat162 h23 = split_hi(v2, v3), l23 = split_lo(v2, v3, h23);
            *(__nv_bfloat162*)(smem + SM_A1H + r0 * PA1 + c0 * 2) = h01;
            *(__nv_bfloat162*)(smem + SM_A1L + r0 * PA1 + c0 * 2) = l01;
            *(__nv_bfloat162*)(smem + SM_A1H + r1 * PA1 + c0 * 2) = h23;
            *(__nv_bfloat162*)(smem + SM_A1L + r1 * PA1 + c0 * 2) = l23;
        }
    __syncthreads();

    // ---- layer 1 ----
    float a2[4][4][4];
    #pragma unroll
    for (int m = 0; m < 4; m++)
        #pragma unroll
        for (int nt = 0; nt < 4; nt++)
            #pragma unroll
            for (int r = 0; r < 4; r++) a2[m][nt][r] = 0.f;
    #pragma unroll 1
    for (int c = 0; c < 8; c++) {
        #pragma unroll
        for (int k16 = 0; k16 < 2; k16++) {
            uint2 bh[4], bl[4];
            #pragma unroll
            for (int nt = 0; nt < 4; nt++) {
                int f = (((c * 2 + k16) * 32 + wid * 4 + nt) * 2) * 32 + lane;
                bh[nt] = g_W1f[f];
                bl[nt] = g_W1f[f + 32];
            }
            #pragma unroll
            for (int m = 0; m < 4; m++) {
                uint32_t ah[4], al[4];
                uint32_t aa = (uint32_t)((m * 16 + aro) * PA1 + (c * 32 + k16 * 16 + aco) * 2);
                ldsm4(ah, smb + SM_A1H + aa);
                ldsm4(al, smb + SM_A1L + aa);
                #pragma unroll
                for (int nt = 0; nt < 4; nt++) {
                    mma16816(a2[m][nt], ah, (const uint32_t*)&bh[nt]);
                    mma16816(a2[m][nt], ah, (const uint32_t*)&bl[nt]);
                    mma16816(a2[m][nt], al, (const uint32_t*)&bh[nt]);
                }
            }
        }
    }

    // ---- epilogue ----
    float* red = (float*)(smem + SM_RED);
    float p[4][2];
    #pragma unroll
    for (int m = 0; m < 4; m++) { p[m][0] = 0.f; p[m][1] = 0.f; }
    #pragma unroll
    for (int m = 0; m < 4; m++)
        #pragma unroll
        for (int nt = 0; nt < 4; nt++) {
            int c0 = wid * 32 + 8 * nt + 2 * tq;
            float w0v = ows[c0], w1v = ows[c0 + 1];
            float bb0 = b1s[c0], bb1 = b1s[c0 + 1];
            float v0 = a2[m][nt][0] + bb0;
            float v1 = a2[m][nt][1] + bb1;
            float v2 = a2[m][nt][2] + bb0;
            float v3 = a2[m][nt][3] + bb1;
            v0 = v0 > 0.f ? v0 : 0.01f * v0;
            v1 = v1 > 0.f ? v1 : 0.01f * v1;
            v2 = v2 > 0.f ? v2 : 0.01f * v2;
            v3 = v3 > 0.f ? v3 : 0.01f * v3;
            p[m][0] = fmaf(v0, w0v, p[m][0]);
            p[m][0] = fmaf(v1, w1v, p[m][0]);
            p[m][1] = fmaf(v2, w0v, p[m][1]);
            p[m][1] = fmaf(v3, w1v, p[m][1]);
        }
    #pragma unroll
    for (int off = 1; off <= 2; off <<= 1)
        #pragma unroll
        for (int m = 0; m < 4; m++) {
            p[m][0] += __shfl_xor_sync(0xffffffffu, p[m][0], off);
            p[m][1] += __shfl_xor_sync(0xffffffffu, p[m][1], off);
        }
    if (tq == 0) {
        #pragma unroll
        for (int m = 0; m < 4; m++) {
            red[wid * 64 + 16 * m + g]     = p[m][0];
            red[wid * 64 + 16 * m + g + 8] = p[m][1];
        }
    }
    __syncthreads();
    if (tid < 64) {
        float s = __ldg(ob);
        #pragma unroll
        for (int w8 = 0; w8 < 8; w8++) s += red[w8 * 64 + tid];
        val[row0 + tid] = s;
    }
}

extern "C" void kernel_launch(void* const* d_in, const int* in_sizes, int n_in,
                              void* d_out, int out_size) {
    const float* obs   = (const float*)d_in[0];
    const float* rnn   = (const float*)d_in[1];
    const float* eAW   = (const float*)d_in[2];
    const float* eAb   = (const float*)d_in[3];
    const float* eMW   = (const float*)d_in[4];
    const float* eMb   = (const float*)d_in[5];
    const float* aWih  = (const float*)d_in[6];
    const float* aWhh  = (const float*)d_in[7];
    const float* abih  = (const float*)d_in[8];
    const float* abhh  = (const float*)d_in[9];
    const float* mWih  = (const float*)d_in[10];
    const float* mWhh  = (const float*)d_in[11];
    const float* mbih  = (const float*)d_in[12];
    const float* mbhh  = (const float*)d_in[13];
    const float* Win   = (const float*)d_in[14];
    const float* bin   = (const float*)d_in[15];
    const float* Wout  = (const float*)d_in[16];
    const float* bout  = (const float*)d_in[17];
    const float* W0    = (const float*)d_in[18];
    const float* b0    = (const float*)d_in[19];
    const float* W1    = (const float*)d_in[20];
    const float* b1    = (const float*)d_in[21];
    const float* oW    = (const float*)d_in[22];
    const float* ob    = (const float*)d_in[23];

    float* out_val = (float*)d_out;
    float* out_h   = (float*)d_out + Nq;

    k_packw<<<178, 256>>>(W0, W1, aWih, aWhh, abih, abhh, eAW, eAb,
                          mWih, mWhh, mbih, mbhh, eMW, eMb, Win, Wout);
    k_packg_x<<<6144, 256>>>(obs);
    k_gru_tc<<<384, 32>>>(rnn, out_h);
    cudaFuncSetAttribute(k_mlp_f, cudaFuncAttributeMaxDynamicSharedMemorySize, SM_TOT);
    k_mlp_f<<<Nq / 64, 256, SM_TOT>>>(obs, bin, bout, b0, b1, oW, ob, out_val);
}